// round 3
// baseline (speedup 1.0000x reference)
#include <cuda_runtime.h>

#define BB 4
#define LL 2048
#define EE 1024
#define HH 16
#define HD 64
#define MM (BB*LL)   // 8192

// Scratch (allocation-free): Q,K,V projections and attention output, each (B,L,E) fp32.
__device__ float g_Q[MM*EE];
__device__ float g_K[MM*EE];
__device__ float g_V[MM*EE];
__device__ float g_A[MM*EE];

// ---------------------------------------------------------------------------
// GEMM: C[m][n] = sum_k A[m][k] * W[n][k] + bias[n]
// A: [Md x Kd] row-major, W: [Nd x Kd] row-major (i.e. computes A @ W^T + b).
// 128x128 block tile, BK=16, 256 threads, 8x8 per-thread micro-tile.
// ---------------------------------------------------------------------------
__global__ __launch_bounds__(256) void gemm_bias_kernel(
    const float* __restrict__ A, const float* __restrict__ W,
    const float* __restrict__ bias, float* __restrict__ C,
    int Md, int Nd, int Kd)
{
    const int BM = 128, BN = 128, BK = 16;
    __shared__ float As[BK][BM];
    __shared__ float Bs[BK][BN];

    int tid = threadIdx.x;
    int m0 = blockIdx.y * BM;
    int n0 = blockIdx.x * BN;
    int tx = tid & 15;        // 0..15 -> 8 cols each
    int ty = tid >> 4;        // 0..15 -> 8 rows each

    float acc[8][8];
    #pragma unroll
    for (int i = 0; i < 8; i++)
        #pragma unroll
        for (int j = 0; j < 8; j++) acc[i][j] = 0.f;

    for (int k0 = 0; k0 < Kd; k0 += BK) {
        // Each tile: 128 rows x 16 k = 512 float4 per operand; 2 float4/thread.
        #pragma unroll
        for (int i = 0; i < 2; i++) {
            int lin = tid + i * 256;          // float4 index 0..511
            int mm = lin >> 2;                // row in tile 0..127
            int kk = (lin & 3) << 2;          // k offset 0,4,8,12
            float4 va = *reinterpret_cast<const float4*>(&A[(m0 + mm) * Kd + k0 + kk]);
            As[kk + 0][mm] = va.x; As[kk + 1][mm] = va.y;
            As[kk + 2][mm] = va.z; As[kk + 3][mm] = va.w;
            float4 vb = *reinterpret_cast<const float4*>(&W[(n0 + mm) * Kd + k0 + kk]);
            Bs[kk + 0][mm] = vb.x; Bs[kk + 1][mm] = vb.y;
            Bs[kk + 2][mm] = vb.z; Bs[kk + 3][mm] = vb.w;
        }
        __syncthreads();

        #pragma unroll
        for (int kk = 0; kk < BK; kk++) {
            float ar[8], br[8];
            #pragma unroll
            for (int i = 0; i < 8; i += 4) {
                float4 v = *reinterpret_cast<const float4*>(&As[kk][ty * 8 + i]);
                ar[i] = v.x; ar[i + 1] = v.y; ar[i + 2] = v.z; ar[i + 3] = v.w;
            }
            #pragma unroll
            for (int j = 0; j < 8; j += 4) {
                float4 v = *reinterpret_cast<const float4*>(&Bs[kk][tx * 8 + j]);
                br[j] = v.x; br[j + 1] = v.y; br[j + 2] = v.z; br[j + 3] = v.w;
            }
            #pragma unroll
            for (int i = 0; i < 8; i++)
                #pragma unroll
                for (int j = 0; j < 8; j++)
                    acc[i][j] += ar[i] * br[j];
        }
        __syncthreads();
    }

    #pragma unroll
    for (int i = 0; i < 8; i++) {
        int m = m0 + ty * 8 + i;
        #pragma unroll
        for (int j = 0; j < 8; j += 4) {
            int n = n0 + tx * 8 + j;
            float4 o;
            o.x = acc[i][j + 0] + bias[n + 0];
            o.y = acc[i][j + 1] + bias[n + 1];
            o.z = acc[i][j + 2] + bias[n + 2];
            o.w = acc[i][j + 3] + bias[n + 3];
            *reinterpret_cast<float4*>(&C[m * Nd + n]) = o;
        }
    }
}

// ---------------------------------------------------------------------------
// Flash attention (fp32, exact online softmax), matching the reference's RAW
// RESHAPE head split: head h of batch b is the contiguous slice
//   Q[b].flat[h*L*HD : (h+1)*L*HD] viewed as (L, HD) row-major.
// So Q/K/V are addressed as a contiguous (B*H, L, HD) tensor.
// Output goes to the STANDARD layout: O[(b*L + l)*E + h*HD + d]
// (reference does transpose(0,2,1,3).reshape on the way out).
// One thread = one query row; block = 128 query rows of one (b,h).
// ---------------------------------------------------------------------------
__global__ __launch_bounds__(128) void attn_kernel(
    const float* __restrict__ Q, const float* __restrict__ K,
    const float* __restrict__ V, const int* __restrict__ mask,
    float* __restrict__ O)
{
    __shared__ float Ks[64][HD];
    __shared__ float Vs[64][HD];
    __shared__ int   ms[64];

    int b = blockIdx.z;
    int h = blockIdx.y;
    int qrow = blockIdx.x * 128 + threadIdx.x;
    int t = threadIdx.x;

    long long hbase = ((long long)(b * HH + h)) * LL * HD;  // contiguous head slab

    // Load this thread's query row, pre-scaled by 1/sqrt(HD) = 0.125.
    float q[HD];
    const float* qp = &Q[hbase + (long long)qrow * HD];
    #pragma unroll
    for (int d = 0; d < HD; d += 4) {
        float4 v = *reinterpret_cast<const float4*>(&qp[d]);
        q[d] = v.x * 0.125f; q[d + 1] = v.y * 0.125f;
        q[d + 2] = v.z * 0.125f; q[d + 3] = v.w * 0.125f;
    }

    float o[HD];
    #pragma unroll
    for (int d = 0; d < HD; d++) o[d] = 0.f;
    float mrun = -1e30f, lrun = 0.f;

    for (int k0 = 0; k0 < LL; k0 += 64) {
        // Load 64x64 K and V tiles: fully contiguous 16KB each.
        const float* kp = &K[hbase + (long long)k0 * HD];
        const float* vp = &V[hbase + (long long)k0 * HD];
        #pragma unroll
        for (int i = 0; i < 8; i++) {
            int lin = t + i * 128;            // float4 idx 0..1023
            reinterpret_cast<float4*>(&Ks[0][0])[lin] =
                reinterpret_cast<const float4*>(kp)[lin];
            reinterpret_cast<float4*>(&Vs[0][0])[lin] =
                reinterpret_cast<const float4*>(vp)[lin];
        }
        if (t < 64) ms[t] = mask[b * LL + k0 + t];
        __syncthreads();

        #pragma unroll 2
        for (int j = 0; j < 64; j++) {
            float s;
            if (ms[j] == 0) {
                s = -1e10f;                   // masked key (uniform branch)
            } else {
                float s0 = 0.f, s1 = 0.f, s2 = 0.f, s3 = 0.f;
                #pragma unroll
                for (int d = 0; d < HD; d += 4) {
                    float4 kv = *reinterpret_cast<const float4*>(&Ks[j][d]);
                    s0 += q[d] * kv.x;  s1 += q[d + 1] * kv.y;
                    s2 += q[d + 2] * kv.z; s3 += q[d + 3] * kv.w;
                }
                s = (s0 + s1) + (s2 + s3);
            }
            if (s > mrun) {
                float corr = __expf(mrun - s);
                lrun *= corr;
                #pragma unroll
                for (int d = 0; d < HD; d++) o[d] *= corr;
                mrun = s;
            }
            float p = __expf(s - mrun);
            if (p > 0.f) {
                lrun += p;
                #pragma unroll
                for (int d = 0; d < HD; d += 4) {
                    float4 vv = *reinterpret_cast<const float4*>(&Vs[j][d]);
                    o[d]     += p * vv.x; o[d + 1] += p * vv.y;
                    o[d + 2] += p * vv.z; o[d + 3] += p * vv.w;
                }
            }
        }
        __syncthreads();
    }

    float inv = 1.f / lrun;
    // Standard-layout output: (b, l, h*HD + d)
    float* op = &O[((long long)(b * LL + qrow)) * EE + h * HD];
    #pragma unroll
    for (int d = 0; d < HD; d += 4) {
        float4 v;
        v.x = o[d] * inv; v.y = o[d + 1] * inv;
        v.z = o[d + 2] * inv; v.w = o[d + 3] * inv;
        *reinterpret_cast<float4*>(&op[d]) = v;
    }
}

// ---------------------------------------------------------------------------
// Launch
// ---------------------------------------------------------------------------
extern "C" void kernel_launch(void* const* d_in, const int* in_sizes, int n_in,
                              void* d_out, int out_size) {
    const float* x    = (const float*)d_in[0];
    const int*   mask = (const int*)  d_in[1];
    const float* Wq   = (const float*)d_in[2];
    const float* bq   = (const float*)d_in[3];
    const float* Wk   = (const float*)d_in[4];
    const float* bk   = (const float*)d_in[5];
    const float* Wv   = (const float*)d_in[6];
    const float* bv   = (const float*)d_in[7];
    const float* Wo   = (const float*)d_in[8];
    const float* bo   = (const float*)d_in[9];
    float* out = (float*)d_out;

    float *Qp, *Kp, *Vp, *Ap;
    cudaGetSymbolAddress((void**)&Qp, g_Q);
    cudaGetSymbolAddress((void**)&Kp, g_K);
    cudaGetSymbolAddress((void**)&Vp, g_V);
    cudaGetSymbolAddress((void**)&Ap, g_A);

    dim3 gemm_grid(EE / 128, MM / 128);   // (8, 64)
    gemm_bias_kernel<<<gemm_grid, 256>>>(x,  Wq, bq, Qp, MM, EE, EE);
    gemm_bias_kernel<<<gemm_grid, 256>>>(x,  Wk, bk, Kp, MM, EE, EE);
    gemm_bias_kernel<<<gemm_grid, 256>>>(x,  Wv, bv, Vp, MM, EE, EE);

    dim3 attn_grid(LL / 128, HH, BB);     // (16, 16, 4)
    attn_kernel<<<attn_grid, 128>>>(Qp, Kp, Vp, mask, Ap);

    gemm_bias_kernel<<<gemm_grid, 256>>>(Ap, Wo, bo, out, MM, EE, EE);
}

// round 4
// speedup vs baseline: 1.2611x; 1.2611x over previous
#include <cuda_runtime.h>

#define BB 4
#define LL 2048
#define EE 1024
#define HH 16
#define HD 64
#define MM (BB*LL)   // 8192

// Scratch (allocation-free): Q,K,V projections and attention output.
__device__ float g_Q[MM*EE];
__device__ float g_K[MM*EE];
__device__ float g_V[MM*EE];
__device__ float g_A[MM*EE];

__device__ __forceinline__ unsigned f2tf32(float v) {
    unsigned u;
    asm("cvt.rna.tf32.f32 %0, %1;" : "=r"(u) : "f"(v));
    return u;
}

__device__ __forceinline__ void mma_tf32(float* c, const unsigned* a, const unsigned* b) {
    asm volatile(
        "mma.sync.aligned.m16n8k8.row.col.f32.tf32.tf32.f32 "
        "{%0,%1,%2,%3}, {%4,%5,%6,%7}, {%8,%9}, {%0,%1,%2,%3};\n"
        : "+f"(c[0]), "+f"(c[1]), "+f"(c[2]), "+f"(c[3])
        : "r"(a[0]), "r"(a[1]), "r"(a[2]), "r"(a[3]), "r"(b[0]), "r"(b[1]));
}

// ---------------------------------------------------------------------------
// TF32 tensor-core GEMM: C[m][n] = sum_k A[m][k]*W[n][k] + bias[n]
// Block tile 128x128, BK=32, 256 threads = 8 warps in 4(m) x 2(n).
// Warp tile 32(m) x 64(n): 2 x 8 m16n8k8 fragments.
// Smem tiles transposed [k][row] with stride 136 (136%32==8 -> conflict-free
// fragment gathers). tf32 conversion at smem-fill time.
// ---------------------------------------------------------------------------
__global__ __launch_bounds__(256) void gemm_tf32_kernel(
    const float* __restrict__ A, const float* __restrict__ W,
    const float* __restrict__ bias, float* __restrict__ C)
{
    const int Kd = EE, Nd = EE;
    __shared__ unsigned As[32][136];
    __shared__ unsigned Bs[32][136];

    int tid = threadIdx.x;
    int m0 = blockIdx.y * 128, n0 = blockIdx.x * 128;
    int w = tid >> 5, lane = tid & 31;
    int wm = (w & 3) * 32;       // warp m offset in block
    int wn = (w >> 2) * 64;      // warp n offset in block
    int r = lane >> 2;           // 0..7
    int cc = lane & 3;           // 0..3

    float acc[2][8][4];
    #pragma unroll
    for (int mi = 0; mi < 2; mi++)
        #pragma unroll
        for (int ni = 0; ni < 8; ni++)
            #pragma unroll
            for (int j = 0; j < 4; j++) acc[mi][ni][j] = 0.f;

    for (int k0 = 0; k0 < Kd; k0 += 32) {
        // Fill As/Bs: 128 rows x 32 k each = 1024 float4; 4 per thread per tile.
        #pragma unroll
        for (int i = 0; i < 4; i++) {
            int lin = tid + i * 256;
            int row = lin >> 3;              // 0..127
            int kq  = (lin & 7) << 2;        // 0,4,...,28
            float4 va = *reinterpret_cast<const float4*>(
                &A[(size_t)(m0 + row) * Kd + k0 + kq]);
            As[kq + 0][row] = f2tf32(va.x);
            As[kq + 1][row] = f2tf32(va.y);
            As[kq + 2][row] = f2tf32(va.z);
            As[kq + 3][row] = f2tf32(va.w);
            float4 vb = *reinterpret_cast<const float4*>(
                &W[(size_t)(n0 + row) * Kd + k0 + kq]);
            Bs[kq + 0][row] = f2tf32(vb.x);
            Bs[kq + 1][row] = f2tf32(vb.y);
            Bs[kq + 2][row] = f2tf32(vb.z);
            Bs[kq + 3][row] = f2tf32(vb.w);
        }
        __syncthreads();

        #pragma unroll
        for (int kk = 0; kk < 32; kk += 8) {
            unsigned af[2][4], bf[8][2];
            #pragma unroll
            for (int mi = 0; mi < 2; mi++) {
                int mb = wm + mi * 16 + r;
                af[mi][0] = As[kk + cc][mb];
                af[mi][1] = As[kk + cc][mb + 8];
                af[mi][2] = As[kk + cc + 4][mb];
                af[mi][3] = As[kk + cc + 4][mb + 8];
            }
            #pragma unroll
            for (int ni = 0; ni < 8; ni++) {
                int nb = wn + ni * 8 + r;
                bf[ni][0] = Bs[kk + cc][nb];
                bf[ni][1] = Bs[kk + cc + 4][nb];
            }
            #pragma unroll
            for (int mi = 0; mi < 2; mi++)
                #pragma unroll
                for (int ni = 0; ni < 8; ni++)
                    mma_tf32(acc[mi][ni], af[mi], bf[ni]);
        }
        __syncthreads();
    }

    // Epilogue: bias + store (float2 per fragment row).
    #pragma unroll
    for (int mi = 0; mi < 2; mi++) {
        int m = m0 + wm + mi * 16 + r;
        #pragma unroll
        for (int ni = 0; ni < 8; ni++) {
            int n = n0 + wn + ni * 8 + cc * 2;
            float2 bv = *reinterpret_cast<const float2*>(&bias[n]);
            float2 o0, o1;
            o0.x = acc[mi][ni][0] + bv.x;  o0.y = acc[mi][ni][1] + bv.y;
            o1.x = acc[mi][ni][2] + bv.x;  o1.y = acc[mi][ni][3] + bv.y;
            *reinterpret_cast<float2*>(&C[(size_t)m * Nd + n]) = o0;
            *reinterpret_cast<float2*>(&C[(size_t)(m + 8) * Nd + n]) = o1;
        }
    }
}

// ---------------------------------------------------------------------------
// Flash attention (fp32, exact online softmax). Raw-reshape head split:
// Q/K/V addressed as contiguous (B*H, L, HD); output to standard (B,L,E).
// One thread = one query row; block = 128 query rows of one (b,h).
// ---------------------------------------------------------------------------
__global__ __launch_bounds__(128) void attn_kernel(
    const float* __restrict__ Q, const float* __restrict__ K,
    const float* __restrict__ V, const int* __restrict__ mask,
    float* __restrict__ O)
{
    __shared__ float Ks[64][HD];
    __shared__ float Vs[64][HD];
    __shared__ int   ms[64];

    int b = blockIdx.z;
    int h = blockIdx.y;
    int qrow = blockIdx.x * 128 + threadIdx.x;
    int t = threadIdx.x;

    long long hbase = ((long long)(b * HH + h)) * LL * HD;

    float q[HD];
    const float* qp = &Q[hbase + (long long)qrow * HD];
    #pragma unroll
    for (int d = 0; d < HD; d += 4) {
        float4 v = *reinterpret_cast<const float4*>(&qp[d]);
        q[d] = v.x * 0.125f; q[d + 1] = v.y * 0.125f;
        q[d + 2] = v.z * 0.125f; q[d + 3] = v.w * 0.125f;
    }

    float o[HD];
    #pragma unroll
    for (int d = 0; d < HD; d++) o[d] = 0.f;
    float mrun = -1e30f, lrun = 0.f;

    for (int k0 = 0; k0 < LL; k0 += 64) {
        const float* kp = &K[hbase + (long long)k0 * HD];
        const float* vp = &V[hbase + (long long)k0 * HD];
        #pragma unroll
        for (int i = 0; i < 8; i++) {
            int lin = t + i * 128;
            reinterpret_cast<float4*>(&Ks[0][0])[lin] =
                reinterpret_cast<const float4*>(kp)[lin];
            reinterpret_cast<float4*>(&Vs[0][0])[lin] =
                reinterpret_cast<const float4*>(vp)[lin];
        }
        if (t < 64) ms[t] = mask[b * LL + k0 + t];
        __syncthreads();

        #pragma unroll 2
        for (int j = 0; j < 64; j++) {
            float s;
            if (ms[j] == 0) {
                s = -1e10f;
            } else {
                float s0 = 0.f, s1 = 0.f, s2 = 0.f, s3 = 0.f;
                #pragma unroll
                for (int d = 0; d < HD; d += 4) {
                    float4 kv = *reinterpret_cast<const float4*>(&Ks[j][d]);
                    s0 += q[d] * kv.x;  s1 += q[d + 1] * kv.y;
                    s2 += q[d + 2] * kv.z; s3 += q[d + 3] * kv.w;
                }
                s = (s0 + s1) + (s2 + s3);
            }
            if (s > mrun) {
                float corr = __expf(mrun - s);
                lrun *= corr;
                #pragma unroll
                for (int d = 0; d < HD; d++) o[d] *= corr;
                mrun = s;
            }
            float p = __expf(s - mrun);
            if (p > 0.f) {
                lrun += p;
                #pragma unroll
                for (int d = 0; d < HD; d += 4) {
                    float4 vv = *reinterpret_cast<const float4*>(&Vs[j][d]);
                    o[d]     += p * vv.x; o[d + 1] += p * vv.y;
                    o[d + 2] += p * vv.z; o[d + 3] += p * vv.w;
                }
            }
        }
        __syncthreads();
    }

    float inv = 1.f / lrun;
    float* op = &O[((long long)(b * LL + qrow)) * EE + h * HD];
    #pragma unroll
    for (int d = 0; d < HD; d += 4) {
        float4 v;
        v.x = o[d] * inv; v.y = o[d + 1] * inv;
        v.z = o[d + 2] * inv; v.w = o[d + 3] * inv;
        *reinterpret_cast<float4*>(&op[d]) = v;
    }
}

// ---------------------------------------------------------------------------
// Launch
// ---------------------------------------------------------------------------
extern "C" void kernel_launch(void* const* d_in, const int* in_sizes, int n_in,
                              void* d_out, int out_size) {
    const float* x    = (const float*)d_in[0];
    const int*   mask = (const int*)  d_in[1];
    const float* Wq   = (const float*)d_in[2];
    const float* bq   = (const float*)d_in[3];
    const float* Wk   = (const float*)d_in[4];
    const float* bk   = (const float*)d_in[5];
    const float* Wv   = (const float*)d_in[6];
    const float* bv   = (const float*)d_in[7];
    const float* Wo   = (const float*)d_in[8];
    const float* bo   = (const float*)d_in[9];
    float* out = (float*)d_out;

    float *Qp, *Kp, *Vp, *Ap;
    cudaGetSymbolAddress((void**)&Qp, g_Q);
    cudaGetSymbolAddress((void**)&Kp, g_K);
    cudaGetSymbolAddress((void**)&Vp, g_V);
    cudaGetSymbolAddress((void**)&Ap, g_A);

    dim3 gemm_grid(EE / 128, MM / 128);   // (8, 64)
    gemm_tf32_kernel<<<gemm_grid, 256>>>(x,  Wq, bq, Qp);
    gemm_tf32_kernel<<<gemm_grid, 256>>>(x,  Wk, bk, Kp);
    gemm_tf32_kernel<<<gemm_grid, 256>>>(x,  Wv, bv, Vp);

    dim3 attn_grid(LL / 128, HH, BB);     // (16, 16, 4)
    attn_kernel<<<attn_grid, 128>>>(Qp, Kp, Vp, mask, Ap);

    gemm_tf32_kernel<<<gemm_grid, 256>>>(Ap, Wo, bo, out);
}

// round 5
// speedup vs baseline: 2.8850x; 2.2876x over previous
#include <cuda_runtime.h>

#define BB 4
#define LL 2048
#define EE 1024
#define HH 16
#define HD 64
#define MM (BB*LL)   // 8192

// Scratch (allocation-free), all tf32-encoded uints.
__device__ unsigned g_Q[MM*EE];
__device__ unsigned g_K[MM*EE];
__device__ unsigned g_V[MM*EE];
__device__ unsigned g_A[MM*EE];
__device__ unsigned g_X[MM*EE];
__device__ unsigned g_Wc[4*EE*EE];

__device__ __forceinline__ unsigned f2tf32(float v) {
    unsigned u;
    asm("cvt.rna.tf32.f32 %0, %1;" : "=r"(u) : "f"(v));
    return u;
}

__device__ __forceinline__ void mma_tf32(float* c,
    unsigned a0, unsigned a1, unsigned a2, unsigned a3,
    unsigned b0, unsigned b1) {
    asm volatile(
        "mma.sync.aligned.m16n8k8.row.col.f32.tf32.tf32.f32 "
        "{%0,%1,%2,%3}, {%4,%5,%6,%7}, {%8,%9}, {%0,%1,%2,%3};\n"
        : "+f"(c[0]), "+f"(c[1]), "+f"(c[2]), "+f"(c[3])
        : "r"(a0), "r"(a1), "r"(a2), "r"(a3), "r"(b0), "r"(b1));
}

__device__ __forceinline__ void cp16(void* dst_smem, const void* src) {
    unsigned d = (unsigned)__cvta_generic_to_shared(dst_smem);
    asm volatile("cp.async.cg.shared.global [%0], [%1], 16;" :: "r"(d), "l"(src));
}

// fp32 -> tf32 bulk conversion
__global__ void conv_tf32_kernel(const float4* __restrict__ in,
                                 uint4* __restrict__ out, int n4) {
    int i = blockIdx.x * blockDim.x + threadIdx.x;
    if (i < n4) {
        float4 v = in[i];
        uint4 u;
        u.x = f2tf32(v.x); u.y = f2tf32(v.y);
        u.z = f2tf32(v.z); u.w = f2tf32(v.w);
        out[i] = u;
    }
}

// ---------------------------------------------------------------------------
// TF32 TC GEMM, cp.async 2-stage pipeline.
// C[m][n] = sum_k A[m][k]*W[n][k] + bias[n];  A,W pre-encoded tf32.
// Block 128x128, BK=32, 256 thr = 8 warps (4m x 2n), warp tile 32x64.
// Smem: natural [row][k] with pad 36 (banks 4r+cc, conflict-free frags).
// store_tf32: 1 -> C uint tf32 (feeds next GEMM/attn), 0 -> C fp32 (d_out).
// ---------------------------------------------------------------------------
#define GSTAGE 4608   // 128*36 words per operand per stage
__global__ __launch_bounds__(256) void gemm_tc(
    const unsigned* __restrict__ A, const unsigned* __restrict__ W,
    const float* __restrict__ bias, void* __restrict__ Cout, int store_tf32)
{
    extern __shared__ unsigned sm[];
    unsigned* As = sm;                 // [2][128][36]
    unsigned* Bs = sm + 2 * GSTAGE;    // [2][128][36]

    int tid = threadIdx.x;
    int m0 = blockIdx.y * 128, n0 = blockIdx.x * 128;
    int w = tid >> 5, lane = tid & 31;
    int wm = (w & 3) * 32, wn = (w >> 2) * 64;
    int r = lane >> 2, cc = lane & 3;

    const unsigned* Abase = A + (size_t)m0 * EE;
    const unsigned* Wbase = W + (size_t)n0 * EE;

    float acc[2][8][4];
    #pragma unroll
    for (int mi = 0; mi < 2; mi++)
        #pragma unroll
        for (int ni = 0; ni < 8; ni++)
            #pragma unroll
            for (int j = 0; j < 4; j++) acc[mi][ni][j] = 0.f;

    int row = tid >> 3;             // 0..31 base rows per i-step handled below
    // fill helper (4 x 16B per operand per stage)
    auto fill = [&](int s, int k0) {
        #pragma unroll
        for (int i = 0; i < 4; i++) {
            int lin = tid + i * 256;
            int rr = lin >> 3;            // 0..127
            int kc = (lin & 7) << 2;      // 0..28
            cp16(&As[s * GSTAGE + rr * 36 + kc], Abase + (size_t)rr * EE + k0 + kc);
            cp16(&Bs[s * GSTAGE + rr * 36 + kc], Wbase + (size_t)rr * EE + k0 + kc);
        }
        asm volatile("cp.async.commit_group;");
    };
    (void)row;

    fill(0, 0);
    for (int it = 0; it < EE / 32; it++) {
        int cur = it & 1;
        if (it + 1 < EE / 32) {
            fill(1 - cur, (it + 1) * 32);
            asm volatile("cp.async.wait_group 1;");
        } else {
            asm volatile("cp.async.wait_group 0;");
        }
        __syncthreads();

        const unsigned* Ac = &As[cur * GSTAGE];
        const unsigned* Bc = &Bs[cur * GSTAGE];
        #pragma unroll
        for (int kk = 0; kk < 32; kk += 8) {
            unsigned af[2][4], bf[8][2];
            #pragma unroll
            for (int mi = 0; mi < 2; mi++) {
                int mb = wm + mi * 16;
                af[mi][0] = Ac[(mb + r) * 36 + kk + cc];
                af[mi][1] = Ac[(mb + 8 + r) * 36 + kk + cc];
                af[mi][2] = Ac[(mb + r) * 36 + kk + cc + 4];
                af[mi][3] = Ac[(mb + 8 + r) * 36 + kk + cc + 4];
            }
            #pragma unroll
            for (int ni = 0; ni < 8; ni++) {
                int nb = wn + ni * 8 + r;
                bf[ni][0] = Bc[nb * 36 + kk + cc];
                bf[ni][1] = Bc[nb * 36 + kk + cc + 4];
            }
            #pragma unroll
            for (int mi = 0; mi < 2; mi++)
                #pragma unroll
                for (int ni = 0; ni < 8; ni++)
                    mma_tf32(acc[mi][ni], af[mi][0], af[mi][1], af[mi][2], af[mi][3],
                             bf[ni][0], bf[ni][1]);
        }
        __syncthreads();
    }

    #pragma unroll
    for (int mi = 0; mi < 2; mi++) {
        int m = m0 + wm + mi * 16 + r;
        #pragma unroll
        for (int ni = 0; ni < 8; ni++) {
            int n = n0 + wn + ni * 8 + cc * 2;
            float2 bv = *reinterpret_cast<const float2*>(&bias[n]);
            float o0 = acc[mi][ni][0] + bv.x, o1 = acc[mi][ni][1] + bv.y;
            float o2 = acc[mi][ni][2] + bv.x, o3 = acc[mi][ni][3] + bv.y;
            if (store_tf32) {
                unsigned* C = (unsigned*)Cout;
                *reinterpret_cast<uint2*>(&C[(size_t)m * EE + n]) =
                    make_uint2(f2tf32(o0), f2tf32(o1));
                *reinterpret_cast<uint2*>(&C[(size_t)(m + 8) * EE + n]) =
                    make_uint2(f2tf32(o2), f2tf32(o3));
            } else {
                float* C = (float*)Cout;
                *reinterpret_cast<float2*>(&C[(size_t)m * EE + n]) = make_float2(o0, o1);
                *reinterpret_cast<float2*>(&C[(size_t)(m + 8) * EE + n]) = make_float2(o2, o3);
            }
        }
    }
}

// ---------------------------------------------------------------------------
// Tensor-core flash attention (tf32 mma, fp32 softmax/accum).
// Raw-reshape head split: Q/K/V contiguous (B*H, L, HD) tf32 uints.
// Block = 64 queries of one (b,h); 4 warps, warp w owns rows [16w,16w+16).
// Per 64-key tile: S = Q K^T (mma), mask+online softmax on C-frags,
// P staged via Ks buffer (tf32), O += P V (mma). Output -> tf32 std layout.
// ---------------------------------------------------------------------------
__global__ __launch_bounds__(128) void attn_tc(
    const unsigned* __restrict__ Q, const unsigned* __restrict__ K,
    const unsigned* __restrict__ V, const int* __restrict__ mask,
    unsigned* __restrict__ O)
{
    __shared__ unsigned Ks[64][68];   // K tile, then reused as P stage
    __shared__ unsigned Vs[64][68];
    __shared__ int ms[64];

    int b = blockIdx.z, h = blockIdx.y;
    int q0 = blockIdx.x * 64;
    int t = threadIdx.x, w = t >> 5, lane = t & 31;
    int r = lane >> 2, cc = lane & 3;
    size_t hbase = ((size_t)(b * HH + h)) * LL * HD;

    // Stage Q tile through Ks, grab A-fragments into registers (all k-steps).
    {
        const uint4* Qg = (const uint4*)(Q + hbase + (size_t)q0 * HD);
        #pragma unroll
        for (int i = 0; i < 8; i++) {
            int lin = t + i * 128;
            int row = lin >> 4, c = (lin & 15) << 2;
            *reinterpret_cast<uint4*>(&Ks[row][c]) = Qg[lin];
        }
    }
    __syncthreads();
    unsigned qa[8][4];
    #pragma unroll
    for (int ks = 0; ks < 8; ks++) {
        qa[ks][0] = Ks[16 * w + r][ks * 8 + cc];
        qa[ks][1] = Ks[16 * w + 8 + r][ks * 8 + cc];
        qa[ks][2] = Ks[16 * w + r][ks * 8 + cc + 4];
        qa[ks][3] = Ks[16 * w + 8 + r][ks * 8 + cc + 4];
    }

    float of[8][4];
    #pragma unroll
    for (int nf = 0; nf < 8; nf++)
        #pragma unroll
        for (int j = 0; j < 4; j++) of[nf][j] = 0.f;
    float mA = -1e30f, mB = -1e30f, lA = 0.f, lB = 0.f;

    for (int k0 = 0; k0 < LL; k0 += 64) {
        __syncthreads();   // prior tile's Ks(P)/Vs reads complete
        const uint4* Kg = (const uint4*)(K + hbase + (size_t)k0 * HD);
        const uint4* Vg = (const uint4*)(V + hbase + (size_t)k0 * HD);
        #pragma unroll
        for (int i = 0; i < 8; i++) {
            int lin = t + i * 128;
            int row = lin >> 4, c = (lin & 15) << 2;
            *reinterpret_cast<uint4*>(&Ks[row][c]) = Kg[lin];
            *reinterpret_cast<uint4*>(&Vs[row][c]) = Vg[lin];
        }
        if (t < 64) ms[t] = mask[b * LL + k0 + t];
        __syncthreads();

        // S = Q K^T for this warp's 16 rows x 64 keys.
        float sc[8][4];
        #pragma unroll
        for (int nf = 0; nf < 8; nf++)
            #pragma unroll
            for (int j = 0; j < 4; j++) sc[nf][j] = 0.f;
        #pragma unroll
        for (int ks = 0; ks < 8; ks++) {
            #pragma unroll
            for (int nf = 0; nf < 8; nf++) {
                unsigned b0 = Ks[nf * 8 + r][ks * 8 + cc];
                unsigned b1 = Ks[nf * 8 + r][ks * 8 + cc + 4];
                mma_tf32(sc[nf], qa[ks][0], qa[ks][1], qa[ks][2], qa[ks][3], b0, b1);
            }
        }

        // scale + mask (in place), row maxima
        float rA = -1e30f, rB = -1e30f;
        #pragma unroll
        for (int nf = 0; nf < 8; nf++) {
            int j0 = nf * 8 + 2 * cc;
            bool u0 = ms[j0] != 0, u1 = ms[j0 + 1] != 0;
            sc[nf][0] = u0 ? sc[nf][0] * 0.125f : -1e10f;
            sc[nf][1] = u1 ? sc[nf][1] * 0.125f : -1e10f;
            sc[nf][2] = u0 ? sc[nf][2] * 0.125f : -1e10f;
            sc[nf][3] = u1 ? sc[nf][3] * 0.125f : -1e10f;
            rA = fmaxf(rA, fmaxf(sc[nf][0], sc[nf][1]));
            rB = fmaxf(rB, fmaxf(sc[nf][2], sc[nf][3]));
        }
        rA = fmaxf(rA, __shfl_xor_sync(0xffffffffu, rA, 1));
        rA = fmaxf(rA, __shfl_xor_sync(0xffffffffu, rA, 2));
        rB = fmaxf(rB, __shfl_xor_sync(0xffffffffu, rB, 1));
        rB = fmaxf(rB, __shfl_xor_sync(0xffffffffu, rB, 2));

        float mAn = fmaxf(mA, rA), mBn = fmaxf(mB, rB);
        float cA = __expf(mA - mAn), cB = __expf(mB - mBn);
        mA = mAn; mB = mBn;
        lA *= cA; lB *= cB;

        float sumA = 0.f, sumB = 0.f;
        unsigned pu[8][4];
        #pragma unroll
        for (int nf = 0; nf < 8; nf++) {
            float p0 = __expf(sc[nf][0] - mA), p1 = __expf(sc[nf][1] - mA);
            float p2 = __expf(sc[nf][2] - mB), p3 = __expf(sc[nf][3] - mB);
            sumA += p0 + p1; sumB += p2 + p3;
            of[nf][0] *= cA; of[nf][1] *= cA; of[nf][2] *= cB; of[nf][3] *= cB;
            pu[nf][0] = f2tf32(p0); pu[nf][1] = f2tf32(p1);
            pu[nf][2] = f2tf32(p2); pu[nf][3] = f2tf32(p3);
        }
        sumA += __shfl_xor_sync(0xffffffffu, sumA, 1);
        sumA += __shfl_xor_sync(0xffffffffu, sumA, 2);
        sumB += __shfl_xor_sync(0xffffffffu, sumB, 1);
        sumB += __shfl_xor_sync(0xffffffffu, sumB, 2);
        lA += sumA; lB += sumB;

        __syncthreads();   // everyone done reading Ks -> reuse as P stage
        #pragma unroll
        for (int nf = 0; nf < 8; nf++) {
            *reinterpret_cast<uint2*>(&Ks[16 * w + r][nf * 8 + 2 * cc]) =
                make_uint2(pu[nf][0], pu[nf][1]);
            *reinterpret_cast<uint2*>(&Ks[16 * w + 8 + r][nf * 8 + 2 * cc]) =
                make_uint2(pu[nf][2], pu[nf][3]);
        }
        __syncwarp();

        // O += P V
        #pragma unroll
        for (int ks = 0; ks < 8; ks++) {
            unsigned pa0 = Ks[16 * w + r][ks * 8 + cc];
            unsigned pa1 = Ks[16 * w + 8 + r][ks * 8 + cc];
            unsigned pa2 = Ks[16 * w + r][ks * 8 + cc + 4];
            unsigned pa3 = Ks[16 * w + 8 + r][ks * 8 + cc + 4];
            #pragma unroll
            for (int nf = 0; nf < 8; nf++) {
                unsigned b0 = Vs[ks * 8 + cc][nf * 8 + r];
                unsigned b1 = Vs[ks * 8 + cc + 4][nf * 8 + r];
                mma_tf32(of[nf], pa0, pa1, pa2, pa3, b0, b1);
            }
        }
    }

    // Normalize + store (standard layout, tf32 for the O-projection GEMM).
    float iA = 1.f / lA, iB = 1.f / lB;
    size_t rowA = (size_t)b * LL + q0 + 16 * w + r;
    #pragma unroll
    for (int nf = 0; nf < 8; nf++) {
        int col = h * HD + nf * 8 + 2 * cc;
        *reinterpret_cast<uint2*>(&O[rowA * EE + col]) =
            make_uint2(f2tf32(of[nf][0] * iA), f2tf32(of[nf][1] * iA));
        *reinterpret_cast<uint2*>(&O[(rowA + 8) * EE + col]) =
            make_uint2(f2tf32(of[nf][2] * iB), f2tf32(of[nf][3] * iB));
    }
}

// ---------------------------------------------------------------------------
// Launch
// ---------------------------------------------------------------------------
extern "C" void kernel_launch(void* const* d_in, const int* in_sizes, int n_in,
                              void* d_out, int out_size) {
    const float* x    = (const float*)d_in[0];
    const int*   mask = (const int*)  d_in[1];
    const float* Wq   = (const float*)d_in[2];
    const float* bq   = (const float*)d_in[3];
    const float* Wk   = (const float*)d_in[4];
    const float* bk   = (const float*)d_in[5];
    const float* Wv   = (const float*)d_in[6];
    const float* bv   = (const float*)d_in[7];
    const float* Wo   = (const float*)d_in[8];
    const float* bo   = (const float*)d_in[9];
    float* out = (float*)d_out;

    unsigned *Qp, *Kp, *Vp, *Ap, *Xp, *Wp;
    cudaGetSymbolAddress((void**)&Qp, g_Q);
    cudaGetSymbolAddress((void**)&Kp, g_K);
    cudaGetSymbolAddress((void**)&Vp, g_V);
    cudaGetSymbolAddress((void**)&Ap, g_A);
    cudaGetSymbolAddress((void**)&Xp, g_X);
    cudaGetSymbolAddress((void**)&Wp, g_Wc);

    static int smem_set = 0;
    const int gemm_smem = 4 * GSTAGE * sizeof(unsigned);   // 73728 B
    if (!smem_set) {
        cudaFuncSetAttribute(gemm_tc, cudaFuncAttributeMaxDynamicSharedMemorySize,
                             gemm_smem);
        smem_set = 1;
    }

    // tf32 pre-conversion
    const int n4x = MM * EE / 4;       // 2,097,152
    const int n4w = EE * EE / 4;       // 262,144
    conv_tf32_kernel<<<(n4x + 255) / 256, 256>>>((const float4*)x,  (uint4*)Xp, n4x);
    conv_tf32_kernel<<<(n4w + 255) / 256, 256>>>((const float4*)Wq, (uint4*)(Wp + 0 * EE * EE), n4w);
    conv_tf32_kernel<<<(n4w + 255) / 256, 256>>>((const float4*)Wk, (uint4*)(Wp + 1 * EE * EE), n4w);
    conv_tf32_kernel<<<(n4w + 255) / 256, 256>>>((const float4*)Wv, (uint4*)(Wp + 2 * EE * EE), n4w);
    conv_tf32_kernel<<<(n4w + 255) / 256, 256>>>((const float4*)Wo, (uint4*)(Wp + 3 * EE * EE), n4w);

    dim3 gemm_grid(EE / 128, MM / 128);   // (8, 64)
    gemm_tc<<<gemm_grid, 256, gemm_smem>>>(Xp, Wp + 0 * EE * EE, bq, Qp, 1);
    gemm_tc<<<gemm_grid, 256, gemm_smem>>>(Xp, Wp + 1 * EE * EE, bk, Kp, 1);
    gemm_tc<<<gemm_grid, 256, gemm_smem>>>(Xp, Wp + 2 * EE * EE, bv, Vp, 1);

    dim3 attn_grid(LL / 64, HH, BB);      // (32, 16, 4)
    attn_tc<<<attn_grid, 128>>>(Qp, Kp, Vp, mask, Ap);

    gemm_tc<<<gemm_grid, 256, gemm_smem>>>(Ap, Wp + 3 * EE * EE, bo, out, 0);
}

// round 7
// speedup vs baseline: 3.4454x; 1.1943x over previous
#include <cuda_runtime.h>

#define BB 4
#define LL 2048
#define EE 1024
#define HH 16
#define HD 64
#define MM (BB*LL)   // 8192

// Scratch (allocation-free), all tf32-encoded uints.
__device__ unsigned g_Q[MM*EE];
__device__ unsigned g_K[MM*EE];
__device__ unsigned g_V[MM*EE];
__device__ unsigned g_A[MM*EE];
__device__ unsigned g_X[MM*EE];
__device__ unsigned g_Wc[4*EE*EE];

__device__ __forceinline__ unsigned f2tf32(float v) {
    unsigned u;
    asm("cvt.rna.tf32.f32 %0, %1;" : "=r"(u) : "f"(v));
    return u;
}

__device__ __forceinline__ void mma_tf32(float* c,
    unsigned a0, unsigned a1, unsigned a2, unsigned a3,
    unsigned b0, unsigned b1) {
    asm volatile(
        "mma.sync.aligned.m16n8k8.row.col.f32.tf32.tf32.f32 "
        "{%0,%1,%2,%3}, {%4,%5,%6,%7}, {%8,%9}, {%0,%1,%2,%3};\n"
        : "+f"(c[0]), "+f"(c[1]), "+f"(c[2]), "+f"(c[3])
        : "r"(a0), "r"(a1), "r"(a2), "r"(a3), "r"(b0), "r"(b1));
}

__device__ __forceinline__ void cp16(void* dst_smem, const void* src) {
    unsigned d = (unsigned)__cvta_generic_to_shared(dst_smem);
    asm volatile("cp.async.cg.shared.global [%0], [%1], 16;" :: "r"(d), "l"(src));
}

// fp32 -> tf32 bulk conversion (x)
__global__ void conv_tf32_kernel(const float4* __restrict__ in,
                                 uint4* __restrict__ out, int n4) {
    int i = blockIdx.x * blockDim.x + threadIdx.x;
    if (i < n4) {
        float4 v = in[i];
        out[i] = make_uint4(f2tf32(v.x), f2tf32(v.y), f2tf32(v.z), f2tf32(v.w));
    }
}

// all 4 weights in one launch (grid.y selects weight)
__global__ void conv_w4_kernel(const float4* __restrict__ w0, const float4* __restrict__ w1,
                               const float4* __restrict__ w2, const float4* __restrict__ w3,
                               uint4* __restrict__ out, int n4w) {
    const float4* src = (blockIdx.y == 0) ? w0 : (blockIdx.y == 1) ? w1
                      : (blockIdx.y == 2) ? w2 : w3;
    int i = blockIdx.x * blockDim.x + threadIdx.x;
    if (i < n4w) {
        float4 v = src[i];
        out[(size_t)blockIdx.y * n4w + i] =
            make_uint4(f2tf32(v.x), f2tf32(v.y), f2tf32(v.z), f2tf32(v.w));
    }
}

// ---------------------------------------------------------------------------
// TF32 TC GEMM, cp.async 2-stage pipeline.
// C[m][n] = (sum_k A[m][k]*W[n][k] + bias[n]) * oscale
// Block tile 128(m) x 256(n), BK=32, 256 thr = 8 warps (2m x 4n),
// warp tile 64x64 (4x8 m16n8k8 fragments) -> 1 LDS word per mma.
// Smem [row][k] pad 36 (banks 4r+cc, conflict-free).
// ---------------------------------------------------------------------------
#define GS_A (128*36)   // words per A stage
#define GS_B (256*36)   // words per B stage
#define GEMM_SMEM ((2*GS_A + 2*GS_B) * 4)   // 110592 B

__global__ __launch_bounds__(256) void gemm_tc(
    const unsigned* __restrict__ A, const unsigned* __restrict__ W,
    const float* __restrict__ bias, void* __restrict__ Cout,
    int store_tf32, float oscale)
{
    extern __shared__ unsigned sm[];
    unsigned* As = sm;                  // [2][128][36]
    unsigned* Bs = sm + 2 * GS_A;       // [2][256][36]

    int tid = threadIdx.x;
    int m0 = blockIdx.y * 128, n0 = blockIdx.x * 256;
    int w = tid >> 5, lane = tid & 31;
    int wm = (w & 1) * 64, wn = (w >> 1) * 64;
    int r = lane >> 2, cc = lane & 3;

    const unsigned* Abase = A + (size_t)m0 * EE;
    const unsigned* Wbase = W + (size_t)n0 * EE;

    float acc[4][8][4];
    #pragma unroll
    for (int mi = 0; mi < 4; mi++)
        #pragma unroll
        for (int ni = 0; ni < 8; ni++)
            #pragma unroll
            for (int j = 0; j < 4; j++) acc[mi][ni][j] = 0.f;

    auto fill = [&](int s, int k0) {
        #pragma unroll
        for (int i = 0; i < 4; i++) {           // A: 1024 chunks
            int lin = tid + i * 256;
            int rr = lin >> 3, kc = (lin & 7) << 2;
            cp16(&As[s * GS_A + rr * 36 + kc], Abase + (size_t)rr * EE + k0 + kc);
        }
        #pragma unroll
        for (int i = 0; i < 8; i++) {           // B: 2048 chunks
            int lin = tid + i * 256;
            int rr = lin >> 3, kc = (lin & 7) << 2;
            cp16(&Bs[s * GS_B + rr * 36 + kc], Wbase + (size_t)rr * EE + k0 + kc);
        }
        asm volatile("cp.async.commit_group;");
    };

    fill(0, 0);
    for (int it = 0; it < EE / 32; it++) {
        int cur = it & 1;
        if (it + 1 < EE / 32) {
            fill(1 - cur, (it + 1) * 32);
            asm volatile("cp.async.wait_group 1;");
        } else {
            asm volatile("cp.async.wait_group 0;");
        }
        __syncthreads();

        const unsigned* Ac = &As[cur * GS_A];
        const unsigned* Bc = &Bs[cur * GS_B];
        #pragma unroll
        for (int kk = 0; kk < 32; kk += 8) {
            unsigned af[4][4], bf[8][2];
            #pragma unroll
            for (int mi = 0; mi < 4; mi++) {
                int mb = wm + mi * 16;
                af[mi][0] = Ac[(mb + r) * 36 + kk + cc];
                af[mi][1] = Ac[(mb + 8 + r) * 36 + kk + cc];
                af[mi][2] = Ac[(mb + r) * 36 + kk + cc + 4];
                af[mi][3] = Ac[(mb + 8 + r) * 36 + kk + cc + 4];
            }
            #pragma unroll
            for (int ni = 0; ni < 8; ni++) {
                int nb = wn + ni * 8 + r;
                bf[ni][0] = Bc[nb * 36 + kk + cc];
                bf[ni][1] = Bc[nb * 36 + kk + cc + 4];
            }
            #pragma unroll
            for (int mi = 0; mi < 4; mi++)
                #pragma unroll
                for (int ni = 0; ni < 8; ni++)
                    mma_tf32(acc[mi][ni], af[mi][0], af[mi][1], af[mi][2], af[mi][3],
                             bf[ni][0], bf[ni][1]);
        }
        __syncthreads();
    }

    #pragma unroll
    for (int mi = 0; mi < 4; mi++) {
        int m = m0 + wm + mi * 16 + r;
        #pragma unroll
        for (int ni = 0; ni < 8; ni++) {
            int n = n0 + wn + ni * 8 + cc * 2;
            float2 bv = *reinterpret_cast<const float2*>(&bias[n]);
            float o0 = (acc[mi][ni][0] + bv.x) * oscale;
            float o1 = (acc[mi][ni][1] + bv.y) * oscale;
            float o2 = (acc[mi][ni][2] + bv.x) * oscale;
            float o3 = (acc[mi][ni][3] + bv.y) * oscale;
            if (store_tf32) {
                unsigned* C = (unsigned*)Cout;
                *reinterpret_cast<uint2*>(&C[(size_t)m * EE + n]) =
                    make_uint2(f2tf32(o0), f2tf32(o1));
                *reinterpret_cast<uint2*>(&C[(size_t)(m + 8) * EE + n]) =
                    make_uint2(f2tf32(o2), f2tf32(o3));
            } else {
                float* C = (float*)Cout;
                *reinterpret_cast<float2*>(&C[(size_t)m * EE + n]) = make_float2(o0, o1);
                *reinterpret_cast<float2*>(&C[(size_t)(m + 8) * EE + n]) = make_float2(o2, o3);
            }
        }
    }
}

// ---------------------------------------------------------------------------
// Tensor-core flash attention (tf32 mma, fp32 softmax/accum).
// Raw-reshape head split: Q/K/V contiguous (B*H, L, HD) tf32 uints;
// Q pre-scaled by 1/8 at projection. Output -> std layout (B,L,E) tf32.
// Block = 128 queries of one (b,h); 4 warps, warp w owns 32 rows (mi=2
// 16-row fragments) -> K/V B-fragments reused across both row blocks.
// P staged through a PER-WARP smem buffer (syncwarp only).
// ---------------------------------------------------------------------------
#define ATTN_SMEM ((64*68 + 64*68 + 4*32*68) * 4 + 64 * 4)   // 69888

__global__ __launch_bounds__(128) void attn_tc(
    const unsigned* __restrict__ Q, const unsigned* __restrict__ K,
    const unsigned* __restrict__ V, const int* __restrict__ mask,
    unsigned* __restrict__ O)
{
    extern __shared__ unsigned smn[];
    unsigned (*Ks)[68] = (unsigned (*)[68])smn;                // [64][68]
    unsigned (*Vs)[68] = (unsigned (*)[68])(smn + 64 * 68);    // [64][68]
    unsigned (*Ps)[68] = (unsigned (*)[68])(smn + 2 * 64 * 68);// [4*32][68]
    int* ms = (int*)(smn + 2 * 64 * 68 + 4 * 32 * 68);

    int b = blockIdx.z, h = blockIdx.y;
    int q0 = blockIdx.x * 128;
    int t = threadIdx.x, w = t >> 5, lane = t & 31;
    int r = lane >> 2, cc = lane & 3;
    size_t hbase = ((size_t)(b * HH + h)) * LL * HD;
    unsigned (*Pw)[68] = &Ps[w * 32];

    // Each warp stages its own 32 Q rows into its P buffer, extracts frags.
    {
        const uint4* Qg = (const uint4*)(Q + hbase + (size_t)(q0 + w * 32) * HD);
        #pragma unroll
        for (int i = 0; i < 16; i++) {
            int lin = lane + i * 32;              // 0..511 uint4
            int row = lin >> 4, c = (lin & 15) << 2;
            *reinterpret_cast<uint4*>(&Pw[row][c]) = Qg[lin];
        }
    }
    __syncwarp();
    unsigned qa[2][8][4];
    #pragma unroll
    for (int mi = 0; mi < 2; mi++)
        #pragma unroll
        for (int ks = 0; ks < 8; ks++) {
            qa[mi][ks][0] = Pw[mi * 16 + r][ks * 8 + cc];
            qa[mi][ks][1] = Pw[mi * 16 + 8 + r][ks * 8 + cc];
            qa[mi][ks][2] = Pw[mi * 16 + r][ks * 8 + cc + 4];
            qa[mi][ks][3] = Pw[mi * 16 + 8 + r][ks * 8 + cc + 4];
        }

    float of[2][8][4];
    #pragma unroll
    for (int mi = 0; mi < 2; mi++)
        #pragma unroll
        for (int nf = 0; nf < 8; nf++)
            #pragma unroll
            for (int j = 0; j < 4; j++) of[mi][nf][j] = 0.f;
    float mA[2] = {-1e30f, -1e30f}, mB[2] = {-1e30f, -1e30f};
    float lA[2] = {0.f, 0.f},       lB[2] = {0.f, 0.f};

    for (int k0 = 0; k0 < LL; k0 += 64) {
        __syncthreads();    // prior tile's Ks/Vs reads complete
        const uint4* Kg = (const uint4*)(K + hbase + (size_t)k0 * HD);
        const uint4* Vg = (const uint4*)(V + hbase + (size_t)k0 * HD);
        #pragma unroll
        for (int i = 0; i < 8; i++) {
            int lin = t + i * 128;
            int row = lin >> 4, c = (lin & 15) << 2;
            *reinterpret_cast<uint4*>(&Ks[row][c]) = Kg[lin];
            *reinterpret_cast<uint4*>(&Vs[row][c]) = Vg[lin];
        }
        if (t < 64) ms[t] = mask[b * LL + k0 + t];
        __syncthreads();

        // S = Q K^T : 32 rows x 64 keys per warp (K-frags shared across mi).
        float sc[2][8][4];
        #pragma unroll
        for (int mi = 0; mi < 2; mi++)
            #pragma unroll
            for (int nf = 0; nf < 8; nf++)
                #pragma unroll
                for (int j = 0; j < 4; j++) sc[mi][nf][j] = 0.f;
        #pragma unroll
        for (int ks = 0; ks < 8; ks++)
            #pragma unroll
            for (int nf = 0; nf < 8; nf++) {
                unsigned b0 = Ks[nf * 8 + r][ks * 8 + cc];
                unsigned b1 = Ks[nf * 8 + r][ks * 8 + cc + 4];
                #pragma unroll
                for (int mi = 0; mi < 2; mi++)
                    mma_tf32(sc[mi][nf], qa[mi][ks][0], qa[mi][ks][1],
                             qa[mi][ks][2], qa[mi][ks][3], b0, b1);
            }

        // mask (Q already carries 1/8 scale) + online softmax per row block
        #pragma unroll
        for (int mi = 0; mi < 2; mi++) {
            float rA = -1e30f, rB = -1e30f;
            #pragma unroll
            for (int nf = 0; nf < 8; nf++) {
                int j0 = nf * 8 + 2 * cc;
                bool u0 = ms[j0] != 0, u1 = ms[j0 + 1] != 0;
                sc[mi][nf][0] = u0 ? sc[mi][nf][0] : -1e10f;
                sc[mi][nf][1] = u1 ? sc[mi][nf][1] : -1e10f;
                sc[mi][nf][2] = u0 ? sc[mi][nf][2] : -1e10f;
                sc[mi][nf][3] = u1 ? sc[mi][nf][3] : -1e10f;
                rA = fmaxf(rA, fmaxf(sc[mi][nf][0], sc[mi][nf][1]));
                rB = fmaxf(rB, fmaxf(sc[mi][nf][2], sc[mi][nf][3]));
            }
            rA = fmaxf(rA, __shfl_xor_sync(0xffffffffu, rA, 1));
            rA = fmaxf(rA, __shfl_xor_sync(0xffffffffu, rA, 2));
            rB = fmaxf(rB, __shfl_xor_sync(0xffffffffu, rB, 1));
            rB = fmaxf(rB, __shfl_xor_sync(0xffffffffu, rB, 2));

            float mAn = fmaxf(mA[mi], rA), mBn = fmaxf(mB[mi], rB);
            float cA = __expf(mA[mi] - mAn), cB = __expf(mB[mi] - mBn);
            mA[mi] = mAn; mB[mi] = mBn;
            lA[mi] *= cA; lB[mi] *= cB;

            float sumA = 0.f, sumB = 0.f;
            #pragma unroll
            for (int nf = 0; nf < 8; nf++) {
                float p0 = __expf(sc[mi][nf][0] - mAn), p1 = __expf(sc[mi][nf][1] - mAn);
                float p2 = __expf(sc[mi][nf][2] - mBn), p3 = __expf(sc[mi][nf][3] - mBn);
                sumA += p0 + p1; sumB += p2 + p3;
                of[mi][nf][0] *= cA; of[mi][nf][1] *= cA;
                of[mi][nf][2] *= cB; of[mi][nf][3] *= cB;
                *reinterpret_cast<uint2*>(&Pw[mi * 16 + r][nf * 8 + 2 * cc]) =
                    make_uint2(f2tf32(p0), f2tf32(p1));
                *reinterpret_cast<uint2*>(&Pw[mi * 16 + 8 + r][nf * 8 + 2 * cc]) =
                    make_uint2(f2tf32(p2), f2tf32(p3));
            }
            sumA += __shfl_xor_sync(0xffffffffu, sumA, 1);
            sumA += __shfl_xor_sync(0xffffffffu, sumA, 2);
            sumB += __shfl_xor_sync(0xffffffffu, sumB, 1);
            sumB += __shfl_xor_sync(0xffffffffu, sumB, 2);
            lA[mi] += sumA; lB[mi] += sumB;
        }
        __syncwarp();   // P buffer is warp-local

        // O += P V  (V-frags shared across mi)
        #pragma unroll
        for (int ks = 0; ks < 8; ks++) {
            unsigned pa[2][4];
            #pragma unroll
            for (int mi = 0; mi < 2; mi++) {
                pa[mi][0] = Pw[mi * 16 + r][ks * 8 + cc];
                pa[mi][1] = Pw[mi * 16 + 8 + r][ks * 8 + cc];
                pa[mi][2] = Pw[mi * 16 + r][ks * 8 + cc + 4];
                pa[mi][3] = Pw[mi * 16 + 8 + r][ks * 8 + cc + 4];
            }
            #pragma unroll
            for (int nf = 0; nf < 8; nf++) {
                unsigned b0 = Vs[ks * 8 + cc][nf * 8 + r];
                unsigned b1 = Vs[ks * 8 + cc + 4][nf * 8 + r];
                #pragma unroll
                for (int mi = 0; mi < 2; mi++)
                    mma_tf32(of[mi][nf], pa[mi][0], pa[mi][1], pa[mi][2], pa[mi][3],
                             b0, b1);
            }
        }
    }

    // Normalize + store (standard layout, tf32 for the O-projection GEMM).
    #pragma unroll
    for (int mi = 0; mi < 2; mi++) {
        float iA = 1.f / lA[mi], iB = 1.f / lB[mi];
        size_t rowA = (size_t)b * LL + q0 + w * 32 + mi * 16 + r;
        #pragma unroll
        for (int nf = 0; nf < 8; nf++) {
            int col = h * HD + nf * 8 + 2 * cc;
            *reinterpret_cast<uint2*>(&O[rowA * EE + col]) =
                make_uint2(f2tf32(of[mi][nf][0] * iA), f2tf32(of[mi][nf][1] * iA));
            *reinterpret_cast<uint2*>(&O[(rowA + 8) * EE + col]) =
                make_uint2(f2tf32(of[mi][nf][2] * iB), f2tf32(of[mi][nf][3] * iB));
        }
    }
}

// ---------------------------------------------------------------------------
// Launch
// ---------------------------------------------------------------------------
extern "C" void kernel_launch(void* const* d_in, const int* in_sizes, int n_in,
                              void* d_out, int out_size) {
    const float* x    = (const float*)d_in[0];
    const int*   mask = (const int*)  d_in[1];
    const float* Wq   = (const float*)d_in[2];
    const float* bq   = (const float*)d_in[3];
    const float* Wk   = (const float*)d_in[4];
    const float* bk   = (const float*)d_in[5];
    const float* Wv   = (const float*)d_in[6];
    const float* bv   = (const float*)d_in[7];
    const float* Wo   = (const float*)d_in[8];
    const float* bo   = (const float*)d_in[9];
    float* out = (float*)d_out;

    unsigned *Qp, *Kp, *Vp, *Ap, *Xp, *Wp;
    cudaGetSymbolAddress((void**)&Qp, g_Q);
    cudaGetSymbolAddress((void**)&Kp, g_K);
    cudaGetSymbolAddress((void**)&Vp, g_V);
    cudaGetSymbolAddress((void**)&Ap, g_A);
    cudaGetSymbolAddress((void**)&Xp, g_X);
    cudaGetSymbolAddress((void**)&Wp, g_Wc);

    static int attr_set = 0;
    if (!attr_set) {
        cudaFuncSetAttribute(gemm_tc, cudaFuncAttributeMaxDynamicSharedMemorySize,
                             GEMM_SMEM);
        cudaFuncSetAttribute(attn_tc, cudaFuncAttributeMaxDynamicSharedMemorySize,
                             ATTN_SMEM);
        attr_set = 1;
    }

    // tf32 pre-conversion
    const int n4x = MM * EE / 4;
    const int n4w = EE * EE / 4;
    conv_tf32_kernel<<<(n4x + 255) / 256, 256>>>((const float4*)x, (uint4*)Xp, n4x);
    dim3 wgrid((n4w + 255) / 256, 4);
    conv_w4_kernel<<<wgrid, 256>>>((const float4*)Wq, (const float4*)Wk,
                                   (const float4*)Wv, (const float4*)Wo,
                                   (uint4*)Wp, n4w);

    dim3 gemm_grid(EE / 256, MM / 128);   // (4, 64)
    gemm_tc<<<gemm_grid, 256, GEMM_SMEM>>>(Xp, Wp + 0 * EE * EE, bq, Qp, 1, 0.125f);
    gemm_tc<<<gemm_grid, 256, GEMM_SMEM>>>(Xp, Wp + 1 * EE * EE, bk, Kp, 1, 1.0f);
    gemm_tc<<<gemm_grid, 256, GEMM_SMEM>>>(Xp, Wp + 2 * EE * EE, bv, Vp, 1, 1.0f);

    dim3 attn_grid(LL / 128, HH, BB);     // (16, 16, 4)
    attn_tc<<<attn_grid, 128, ATTN_SMEM>>>(Qp, Kp, Vp, mask, Ap);

    gemm_tc<<<gemm_grid, 256, GEMM_SMEM>>>(Ap, Wp + 3 * EE * EE, bo, out, 0, 1.0f);
}

// round 9
// speedup vs baseline: 3.6811x; 1.0684x over previous
#include <cuda_runtime.h>

#define BB 4
#define LL 2048
#define EE 1024
#define HH 16
#define HD 64
#define MM (BB*LL)   // 8192

// Scratch (allocation-free), all tf32-encoded uints.
__device__ unsigned g_Q[MM*EE];
__device__ unsigned g_K[MM*EE];
__device__ unsigned g_V[MM*EE];
__device__ unsigned g_A[MM*EE];
__device__ unsigned g_X[MM*EE];
__device__ unsigned g_Wc[4*EE*EE];
__device__ int g_idx[BB*LL];
__device__ int g_cnt[BB];

__device__ __forceinline__ unsigned f2tf32(float v) {
    unsigned u;
    asm("cvt.rna.tf32.f32 %0, %1;" : "=r"(u) : "f"(v));
    return u;
}

__device__ __forceinline__ void mma_tf32(float* c,
    unsigned a0, unsigned a1, unsigned a2, unsigned a3,
    unsigned b0, unsigned b1) {
    asm volatile(
        "mma.sync.aligned.m16n8k8.row.col.f32.tf32.tf32.f32 "
        "{%0,%1,%2,%3}, {%4,%5,%6,%7}, {%8,%9}, {%0,%1,%2,%3};\n"
        : "+f"(c[0]), "+f"(c[1]), "+f"(c[2]), "+f"(c[3])
        : "r"(a0), "r"(a1), "r"(a2), "r"(a3), "r"(b0), "r"(b1));
}

__device__ __forceinline__ void cp16(void* dst_smem, const void* src) {
    unsigned d = (unsigned)__cvta_generic_to_shared(dst_smem);
    asm volatile("cp.async.cg.shared.global [%0], [%1], 16;" :: "r"(d), "l"(src));
}

// fp32 -> tf32 bulk conversion (x)
__global__ void conv_tf32_kernel(const float4* __restrict__ in,
                                 uint4* __restrict__ out, int n4) {
    int i = blockIdx.x * blockDim.x + threadIdx.x;
    if (i < n4) {
        float4 v = in[i];
        out[i] = make_uint4(f2tf32(v.x), f2tf32(v.y), f2tf32(v.z), f2tf32(v.w));
    }
}

// all 4 weights in one launch (grid.y selects weight)
__global__ void conv_w4_kernel(const float4* __restrict__ w0, const float4* __restrict__ w1,
                               const float4* __restrict__ w2, const float4* __restrict__ w3,
                               uint4* __restrict__ out, int n4w) {
    const float4* src = (blockIdx.y == 0) ? w0 : (blockIdx.y == 1) ? w1
                      : (blockIdx.y == 2) ? w2 : w3;
    int i = blockIdx.x * blockDim.x + threadIdx.x;
    if (i < n4w) {
        float4 v = src[i];
        out[(size_t)blockIdx.y * n4w + i] =
            make_uint4(f2tf32(v.x), f2tf32(v.y), f2tf32(v.z), f2tf32(v.w));
    }
}

// ---------------------------------------------------------------------------
// Per-batch mask compaction: idx[b][0..cnt) = positions with mask!=0.
// One block per batch, 1024 threads x 2 elements, warp+block scan.
// Exact: masked keys contribute exp(-1e10 - m) == 0 in fp32.
// ---------------------------------------------------------------------------
__global__ __launch_bounds__(1024) void compact_mask_kernel(
    const int* __restrict__ mask, int* __restrict__ idx, int* __restrict__ cnt)
{
    __shared__ int wsum[32];
    int b = blockIdx.x, t = threadIdx.x;
    int lane = t & 31, w = t >> 5;

    int v0 = mask[b * LL + 2 * t];
    int v1 = mask[b * LL + 2 * t + 1];
    int n = (v0 != 0) + (v1 != 0);

    int s = n;
    #pragma unroll
    for (int d = 1; d < 32; d <<= 1) {
        int x = __shfl_up_sync(0xffffffffu, s, d);
        if (lane >= d) s += x;
    }
    if (lane == 31) wsum[w] = s;
    __syncthreads();
    if (w == 0) {
        int x = wsum[lane];
        #pragma unroll
        for (int d = 1; d < 32; d <<= 1) {
            int y = __shfl_up_sync(0xffffffffu, x, d);
            if (lane >= d) x += y;
        }
        wsum[lane] = x;
    }
    __syncthreads();

    int base = (w > 0 ? wsum[w - 1] : 0) + (s - n);
    int p = base;
    if (v0) idx[b * LL + p++] = 2 * t;
    if (v1) idx[b * LL + p++] = 2 * t + 1;
    if (t == 1023) cnt[b] = wsum[31];
}

// ---------------------------------------------------------------------------
// TF32 TC GEMM, cp.async 2-stage pipeline (unchanged from R7-passing).
// C[m][n] = (sum_k A[m][k]*W[n][k] + bias[n]) * oscale
// Block tile 128(m) x 256(n), BK=32, 256 thr = 8 warps (2m x 4n),
// warp tile 64x64 (4x8 m16n8k8 fragments).
// ---------------------------------------------------------------------------
#define GS_A (128*36)
#define GS_B (256*36)
#define GEMM_SMEM ((2*GS_A + 2*GS_B) * 4)   // 110592 B

__global__ __launch_bounds__(256) void gemm_tc(
    const unsigned* __restrict__ A, const unsigned* __restrict__ W,
    const float* __restrict__ bias, void* __restrict__ Cout,
    int store_tf32, float oscale)
{
    extern __shared__ unsigned sm[];
    unsigned* As = sm;
    unsigned* Bs = sm + 2 * GS_A;

    int tid = threadIdx.x;
    int m0 = blockIdx.y * 128, n0 = blockIdx.x * 256;
    int w = tid >> 5, lane = tid & 31;
    int wm = (w & 1) * 64, wn = (w >> 1) * 64;
    int r = lane >> 2, cc = lane & 3;

    const unsigned* Abase = A + (size_t)m0 * EE;
    const unsigned* Wbase = W + (size_t)n0 * EE;

    float acc[4][8][4];
    #pragma unroll
    for (int mi = 0; mi < 4; mi++)
        #pragma unroll
        for (int ni = 0; ni < 8; ni++)
            #pragma unroll
            for (int j = 0; j < 4; j++) acc[mi][ni][j] = 0.f;

    auto fill = [&](int s, int k0) {
        #pragma unroll
        for (int i = 0; i < 4; i++) {
            int lin = tid + i * 256;
            int rr = lin >> 3, kc = (lin & 7) << 2;
            cp16(&As[s * GS_A + rr * 36 + kc], Abase + (size_t)rr * EE + k0 + kc);
        }
        #pragma unroll
        for (int i = 0; i < 8; i++) {
            int lin = tid + i * 256;
            int rr = lin >> 3, kc = (lin & 7) << 2;
            cp16(&Bs[s * GS_B + rr * 36 + kc], Wbase + (size_t)rr * EE + k0 + kc);
        }
        asm volatile("cp.async.commit_group;");
    };

    fill(0, 0);
    for (int it = 0; it < EE / 32; it++) {
        int cur = it & 1;
        if (it + 1 < EE / 32) {
            fill(1 - cur, (it + 1) * 32);
            asm volatile("cp.async.wait_group 1;");
        } else {
            asm volatile("cp.async.wait_group 0;");
        }
        __syncthreads();

        const unsigned* Ac = &As[cur * GS_A];
        const unsigned* Bc = &Bs[cur * GS_B];
        #pragma unroll
        for (int kk = 0; kk < 32; kk += 8) {
            unsigned af[4][4], bf[8][2];
            #pragma unroll
            for (int mi = 0; mi < 4; mi++) {
                int mb = wm + mi * 16;
                af[mi][0] = Ac[(mb + r) * 36 + kk + cc];
                af[mi][1] = Ac[(mb + 8 + r) * 36 + kk + cc];
                af[mi][2] = Ac[(mb + r) * 36 + kk + cc + 4];
                af[mi][3] = Ac[(mb + 8 + r) * 36 + kk + cc + 4];
            }
            #pragma unroll
            for (int ni = 0; ni < 8; ni++) {
                int nb = wn + ni * 8 + r;
                bf[ni][0] = Bc[nb * 36 + kk + cc];
                bf[ni][1] = Bc[nb * 36 + kk + cc + 4];
            }
            #pragma unroll
            for (int mi = 0; mi < 4; mi++)
                #pragma unroll
                for (int ni = 0; ni < 8; ni++)
                    mma_tf32(acc[mi][ni], af[mi][0], af[mi][1], af[mi][2], af[mi][3],
                             bf[ni][0], bf[ni][1]);
        }
        __syncthreads();
    }

    #pragma unroll
    for (int mi = 0; mi < 4; mi++) {
        int m = m0 + wm + mi * 16 + r;
        #pragma unroll
        for (int ni = 0; ni < 8; ni++) {
            int n = n0 + wn + ni * 8 + cc * 2;
            float2 bv = *reinterpret_cast<const float2*>(&bias[n]);
            float o0 = (acc[mi][ni][0] + bv.x) * oscale;
            float o1 = (acc[mi][ni][1] + bv.y) * oscale;
            float o2 = (acc[mi][ni][2] + bv.x) * oscale;
            float o3 = (acc[mi][ni][3] + bv.y) * oscale;
            if (store_tf32) {
                unsigned* C = (unsigned*)Cout;
                *reinterpret_cast<uint2*>(&C[(size_t)m * EE + n]) =
                    make_uint2(f2tf32(o0), f2tf32(o1));
                *reinterpret_cast<uint2*>(&C[(size_t)(m + 8) * EE + n]) =
                    make_uint2(f2tf32(o2), f2tf32(o3));
            } else {
                float* C = (float*)Cout;
                *reinterpret_cast<float2*>(&C[(size_t)m * EE + n]) = make_float2(o0, o1);
                *reinterpret_cast<float2*>(&C[(size_t)(m + 8) * EE + n]) = make_float2(o2, o3);
            }
        }
    }
}

// ---------------------------------------------------------------------------
// Tensor-core flash attention over COMPACTED keys (tf32 mma, fp32 softmax).
// Only unmasked keys are processed (exact — masked keys contribute 0).
// K/V rows gathered by per-batch index list; pad slots use ms=0 -> -1e10.
// ---------------------------------------------------------------------------
#define ATTN_SMEM ((64*68 + 64*68 + 4*32*68) * 4 + 64 * 4 + 64 * 4)

__global__ __launch_bounds__(128) void attn_tc(
    const unsigned* __restrict__ Q, const unsigned* __restrict__ K,
    const unsigned* __restrict__ V, const int* __restrict__ idxp,
    const int* __restrict__ cntp, unsigned* __restrict__ O)
{
    extern __shared__ unsigned smn[];
    unsigned (*Ks)[68] = (unsigned (*)[68])smn;                 // [64][68]
    unsigned (*Vs)[68] = (unsigned (*)[68])(smn + 64 * 68);     // [64][68]
    unsigned (*Ps)[68] = (unsigned (*)[68])(smn + 2 * 64 * 68); // [4*32][68]
    int* ms = (int*)(smn + 2 * 64 * 68 + 4 * 32 * 68);          // [64]
    int* keyrow = ms + 64;                                      // [64]

    int b = blockIdx.z, h = blockIdx.y;
    int q0 = blockIdx.x * 128;
    int t = threadIdx.x, w = t >> 5, lane = t & 31;
    int r = lane >> 2, cc = lane & 3;
    size_t hbase = ((size_t)(b * HH + h)) * LL * HD;
    unsigned (*Pw)[68] = &Ps[w * 32];

    int cnt = cntp[b];
    int ntiles = (cnt + 63) >> 6;

    // Each warp stages its own 32 Q rows into its P buffer, extracts frags.
    {
        const uint4* Qg = (const uint4*)(Q + hbase + (size_t)(q0 + w * 32) * HD);
        #pragma unroll
        for (int i = 0; i < 16; i++) {
            int lin = lane + i * 32;
            int row = lin >> 4, c = (lin & 15) << 2;
            *reinterpret_cast<uint4*>(&Pw[row][c]) = Qg[lin];
        }
    }
    __syncwarp();
    unsigned qa[2][8][4];
    #pragma unroll
    for (int mi = 0; mi < 2; mi++)
        #pragma unroll
        for (int ks = 0; ks < 8; ks++) {
            qa[mi][ks][0] = Pw[mi * 16 + r][ks * 8 + cc];
            qa[mi][ks][1] = Pw[mi * 16 + 8 + r][ks * 8 + cc];
            qa[mi][ks][2] = Pw[mi * 16 + r][ks * 8 + cc + 4];
            qa[mi][ks][3] = Pw[mi * 16 + 8 + r][ks * 8 + cc + 4];
        }

    float of[2][8][4];
    #pragma unroll
    for (int mi = 0; mi < 2; mi++)
        #pragma unroll
        for (int nf = 0; nf < 8; nf++)
            #pragma unroll
            for (int j = 0; j < 4; j++) of[mi][nf][j] = 0.f;
    float mA[2] = {-1e30f, -1e30f}, mB[2] = {-1e30f, -1e30f};
    float lA[2] = {0.f, 0.f},       lB[2] = {0.f, 0.f};

    for (int tt = 0; tt < ntiles; tt++) {
        int k0 = tt * 64;
        __syncthreads();    // prior tile's Ks/Vs/keyrow reads complete
        if (t < 64) {
            int slot = k0 + t;
            keyrow[t] = (slot < cnt) ? idxp[b * LL + slot] : 0;
            ms[t] = (slot < cnt);
        }
        __syncthreads();

        // Gather 64 K/V rows by compacted index (256B contiguous per row).
        #pragma unroll
        for (int i = 0; i < 8; i++) {
            int lin = t + i * 128;
            int row = lin >> 4, chunk = lin & 15, c = chunk << 2;
            size_t rbase = hbase + (size_t)keyrow[row] * HD;
            *reinterpret_cast<uint4*>(&Ks[row][c]) =
                ((const uint4*)(K + rbase))[chunk];
            *reinterpret_cast<uint4*>(&Vs[row][c]) =
                ((const uint4*)(V + rbase))[chunk];
        }
        __syncthreads();

        // S = Q K^T : 32 rows x 64 keys per warp (K-frags shared across mi).
        float sc[2][8][4];
        #pragma unroll
        for (int mi = 0; mi < 2; mi++)
            #pragma unroll
            for (int nf = 0; nf < 8; nf++)
                #pragma unroll
                for (int j = 0; j < 4; j++) sc[mi][nf][j] = 0.f;
        #pragma unroll
        for (int ks = 0; ks < 8; ks++)
            #pragma unroll
            for (int nf = 0; nf < 8; nf++) {
                unsigned b0 = Ks[nf * 8 + r][ks * 8 + cc];
                unsigned b1 = Ks[nf * 8 + r][ks * 8 + cc + 4];
                #pragma unroll
                for (int mi = 0; mi < 2; mi++)
                    mma_tf32(sc[mi][nf], qa[mi][ks][0], qa[mi][ks][1],
                             qa[mi][ks][2], qa[mi][ks][3], b0, b1);
            }

        // pad-mask (Q already carries 1/8 scale) + online softmax
        #pragma unroll
        for (int mi = 0; mi < 2; mi++) {
            float rA = -1e30f, rB = -1e30f;
            #pragma unroll
            for (int nf = 0; nf < 8; nf++) {
                int j0 = nf * 8 + 2 * cc;
                bool u0 = ms[j0] != 0, u1 = ms[j0 + 1] != 0;
                sc[mi][nf][0] = u0 ? sc[mi][nf][0] : -1e10f;
                sc[mi][nf][1] = u1 ? sc[mi][nf][1] : -1e10f;
                sc[mi][nf][2] = u0 ? sc[mi][nf][2] : -1e10f;
                sc[mi][nf][3] = u1 ? sc[mi][nf][3] : -1e10f;
                rA = fmaxf(rA, fmaxf(sc[mi][nf][0], sc[mi][nf][1]));
                rB = fmaxf(rB, fmaxf(sc[mi][nf][2], sc[mi][nf][3]));
            }
            rA = fmaxf(rA, __shfl_xor_sync(0xffffffffu, rA, 1));
            rA = fmaxf(rA, __shfl_xor_sync(0xffffffffu, rA, 2));
            rB = fmaxf(rB, __shfl_xor_sync(0xffffffffu, rB, 1));
            rB = fmaxf(rB, __shfl_xor_sync(0xffffffffu, rB, 2));

            float mAn = fmaxf(mA[mi], rA), mBn = fmaxf(mB[mi], rB);
            float cA = __expf(mA[mi] - mAn), cB = __expf(mB[mi] - mBn);
            mA[mi] = mAn; mB[mi] = mBn;
            lA[mi] *= cA; lB[mi] *= cB;

            float sumA = 0.f, sumB = 0.f;
            #pragma unroll
            for (int nf = 0; nf < 8; nf++) {
                float p0 = __expf(sc[mi][nf][0] - mAn), p1 = __expf(sc[mi][nf][1] - mAn);
                float p2 = __expf(sc[mi][nf][2] - mBn), p3 = __expf(sc[mi][nf][3] - mBn);
                sumA += p0 + p1; sumB += p2 + p3;
                of[mi][nf][0] *= cA; of[mi][nf][1] *= cA;
                of[mi][nf][2] *= cB; of[mi][nf][3] *= cB;
                *reinterpret_cast<uint2*>(&Pw[mi * 16 + r][nf * 8 + 2 * cc]) =
                    make_uint2(f2tf32(p0), f2tf32(p1));
                *reinterpret_cast<uint2*>(&Pw[mi * 16 + 8 + r][nf * 8 + 2 * cc]) =
                    make_uint2(f2tf32(p2), f2tf32(p3));
            }
            sumA += __shfl_xor_sync(0xffffffffu, sumA, 1);
            sumA += __shfl_xor_sync(0xffffffffu, sumA, 2);
            sumB += __shfl_xor_sync(0xffffffffu, sumB, 1);
            sumB += __shfl_xor_sync(0xffffffffu, sumB, 2);
            lA[mi] += sumA; lB[mi] += sumB;
        }
        __syncwarp();   // P buffer is warp-local

        // O += P V  (V-frags shared across mi)
        #pragma unroll
        for (int ks = 0; ks < 8; ks++) {
            unsigned pa[2][4];
            #pragma unroll
            for (int mi = 0; mi < 2; mi++) {
                pa[mi][0] = Pw[mi * 16 + r][ks * 8 + cc];
                pa[mi][1] = Pw[mi * 16 + 8 + r][ks * 8 + cc];
                pa[mi][2] = Pw[mi * 16 + r][ks * 8 + cc + 4];
                pa[mi][3] = Pw[mi * 16 + 8 + r][ks * 8 + cc + 4];
            }
            #pragma unroll
            for (int nf = 0; nf < 8; nf++) {
                unsigned b0 = Vs[ks * 8 + cc][nf * 8 + r];
                unsigned b1 = Vs[ks * 8 + cc + 4][nf * 8 + r];
                #pragma unroll
                for (int mi = 0; mi < 2; mi++)
                    mma_tf32(of[mi][nf], pa[mi][0], pa[mi][1], pa[mi][2], pa[mi][3],
                             b0, b1);
            }
        }
    }

    // Normalize + store (standard layout, tf32 for the O-projection GEMM).
    #pragma unroll
    for (int mi = 0; mi < 2; mi++) {
        float iA = 1.f / lA[mi], iB = 1.f / lB[mi];
        size_t rowA = (size_t)b * LL + q0 + w * 32 + mi * 16 + r;
        #pragma unroll
        for (int nf = 0; nf < 8; nf++) {
            int col = h * HD + nf * 8 + 2 * cc;
            *reinterpret_cast<uint2*>(&O[rowA * EE + col]) =
                make_uint2(f2tf32(of[mi][nf][0] * iA), f2tf32(of[mi][nf][1] * iA));
            *reinterpret_cast<uint2*>(&O[(rowA + 8) * EE + col]) =
                make_uint2(f2tf32(of[mi][nf][2] * iB), f2tf32(of[mi][nf][3] * iB));
        }
    }
}

// ---------------------------------------------------------------------------
// Launch
// ---------------------------------------------------------------------------
extern "C" void kernel_launch(void* const* d_in, const int* in_sizes, int n_in,
                              void* d_out, int out_size) {
    const float* x    = (const float*)d_in[0];
    const int*   mask = (const int*)  d_in[1];
    const float* Wq   = (const float*)d_in[2];
    const float* bq   = (const float*)d_in[3];
    const float* Wk   = (const float*)d_in[4];
    const float* bk   = (const float*)d_in[5];
    const float* Wv   = (const float*)d_in[6];
    const float* bv   = (const float*)d_in[7];
    const float* Wo   = (const float*)d_in[8];
    const float* bo   = (const float*)d_in[9];
    float* out = (float*)d_out;

    unsigned *Qp, *Kp, *Vp, *Ap, *Xp, *Wp;
    int *idxp, *cntp;
    cudaGetSymbolAddress((void**)&Qp, g_Q);
    cudaGetSymbolAddress((void**)&Kp, g_K);
    cudaGetSymbolAddress((void**)&Vp, g_V);
    cudaGetSymbolAddress((void**)&Ap, g_A);
    cudaGetSymbolAddress((void**)&Xp, g_X);
    cudaGetSymbolAddress((void**)&Wp, g_Wc);
    cudaGetSymbolAddress((void**)&idxp, g_idx);
    cudaGetSymbolAddress((void**)&cntp, g_cnt);

    static int attr_set = 0;
    if (!attr_set) {
        cudaFuncSetAttribute(gemm_tc, cudaFuncAttributeMaxDynamicSharedMemorySize,
                             GEMM_SMEM);
        cudaFuncSetAttribute(attn_tc, cudaFuncAttributeMaxDynamicSharedMemorySize,
                             ATTN_SMEM);
        attr_set = 1;
    }

    // tf32 pre-conversion + mask compaction
    const int n4x = MM * EE / 4;
    const int n4w = EE * EE / 4;
    conv_tf32_kernel<<<(n4x + 255) / 256, 256>>>((const float4*)x, (uint4*)Xp, n4x);
    dim3 wgrid((n4w + 255) / 256, 4);
    conv_w4_kernel<<<wgrid, 256>>>((const float4*)Wq, (const float4*)Wk,
                                   (const float4*)Wv, (const float4*)Wo,
                                   (uint4*)Wp, n4w);
    compact_mask_kernel<<<BB, 1024>>>(mask, idxp, cntp);

    dim3 gemm_grid(EE / 256, MM / 128);   // (4, 64)
    gemm_tc<<<gemm_grid, 256, GEMM_SMEM>>>(Xp, Wp + 0 * EE * EE, bq, Qp, 1, 0.125f);
    gemm_tc<<<gemm_grid, 256, GEMM_SMEM>>>(Xp, Wp + 1 * EE * EE, bk, Kp, 1, 1.0f);
    gemm_tc<<<gemm_grid, 256, GEMM_SMEM>>>(Xp, Wp + 2 * EE * EE, bv, Vp, 1, 1.0f);

    dim3 attn_grid(LL / 128, HH, BB);     // (16, 16, 4)
    attn_tc<<<attn_grid, 128, ATTN_SMEM>>>(Qp, Kp, Vp, idxp, cntp, Ap);

    gemm_tc<<<gemm_grid, 256, GEMM_SMEM>>>(Ap, Wp + 3 * EE * EE, bo, out, 0, 1.0f);
}

// round 11
// speedup vs baseline: 4.5457x; 1.2349x over previous
#include <cuda_runtime.h>

#define BB 4
#define LL 2048
#define EE 1024
#define HH 16
#define HD 64
#define MM (BB*LL)   // 8192

// Scratch (allocation-free), all tf32-encoded uints.
__device__ unsigned g_Q[MM*EE];
__device__ unsigned g_K[MM*EE];
__device__ unsigned g_V[MM*EE];
__device__ unsigned g_A[MM*EE];
__device__ unsigned g_X[MM*EE];
__device__ unsigned g_Wc[4*EE*EE];
__device__ int g_idx[BB*LL];
__device__ int g_cnt[BB];

__device__ __forceinline__ unsigned f2tf32(float v) {
    unsigned u;
    asm("cvt.rna.tf32.f32 %0, %1;" : "=r"(u) : "f"(v));
    return u;
}

__device__ __forceinline__ void mma_tf32(float* c,
    unsigned a0, unsigned a1, unsigned a2, unsigned a3,
    unsigned b0, unsigned b1) {
    asm volatile(
        "mma.sync.aligned.m16n8k8.row.col.f32.tf32.tf32.f32 "
        "{%0,%1,%2,%3}, {%4,%5,%6,%7}, {%8,%9}, {%0,%1,%2,%3};\n"
        : "+f"(c[0]), "+f"(c[1]), "+f"(c[2]), "+f"(c[3])
        : "r"(a0), "r"(a1), "r"(a2), "r"(a3), "r"(b0), "r"(b1));
}

__device__ __forceinline__ void cp16(void* dst_smem, const void* src) {
    unsigned d = (unsigned)__cvta_generic_to_shared(dst_smem);
    asm volatile("cp.async.cg.shared.global [%0], [%1], 16;" :: "r"(d), "l"(src));
}

// fp32 -> tf32 bulk conversion (x)
__global__ void conv_tf32_kernel(const float4* __restrict__ in,
                                 uint4* __restrict__ out, int n4) {
    int i = blockIdx.x * blockDim.x + threadIdx.x;
    if (i < n4) {
        float4 v = in[i];
        out[i] = make_uint4(f2tf32(v.x), f2tf32(v.y), f2tf32(v.z), f2tf32(v.w));
    }
}

// all 4 weights in one launch (grid.y selects weight)
__global__ void conv_w4_kernel(const float4* __restrict__ w0, const float4* __restrict__ w1,
                               const float4* __restrict__ w2, const float4* __restrict__ w3,
                               uint4* __restrict__ out, int n4w) {
    const float4* src = (blockIdx.y == 0) ? w0 : (blockIdx.y == 1) ? w1
                      : (blockIdx.y == 2) ? w2 : w3;
    int i = blockIdx.x * blockDim.x + threadIdx.x;
    if (i < n4w) {
        float4 v = src[i];
        out[(size_t)blockIdx.y * n4w + i] =
            make_uint4(f2tf32(v.x), f2tf32(v.y), f2tf32(v.z), f2tf32(v.w));
    }
}

// ---------------------------------------------------------------------------
// Per-batch mask compaction: idx[b][0..cnt) = pseudo-positions with mask!=0.
// ---------------------------------------------------------------------------
__global__ __launch_bounds__(1024) void compact_mask_kernel(
    const int* __restrict__ mask, int* __restrict__ idx, int* __restrict__ cnt)
{
    __shared__ int wsum[32];
    int b = blockIdx.x, t = threadIdx.x;
    int lane = t & 31, w = t >> 5;

    int v0 = mask[b * LL + 2 * t];
    int v1 = mask[b * LL + 2 * t + 1];
    int n = (v0 != 0) + (v1 != 0);

    int s = n;
    #pragma unroll
    for (int d = 1; d < 32; d <<= 1) {
        int x = __shfl_up_sync(0xffffffffu, s, d);
        if (lane >= d) s += x;
    }
    if (lane == 31) wsum[w] = s;
    __syncthreads();
    if (w == 0) {
        int x = wsum[lane];
        #pragma unroll
        for (int d = 1; d < 32; d <<= 1) {
            int y = __shfl_up_sync(0xffffffffu, x, d);
            if (lane >= d) x += y;
        }
        wsum[lane] = x;
    }
    __syncthreads();

    int base = (w > 0 ? wsum[w - 1] : 0) + (s - n);
    int p = base;
    if (v0) idx[b * LL + p++] = 2 * t;
    if (v1) idx[b * LL + p++] = 2 * t + 1;
    if (t == 1023) cnt[b] = wsum[31];
}

// ---------------------------------------------------------------------------
// Shared TF32 TC GEMM body: 128x256 CTA tile, BK=32, 8 warps (2m x 4n),
// warp tile 64x64, cp.async 2-stage.
// ---------------------------------------------------------------------------
#define GS_A (128*36)
#define GS_B (256*36)
#define GEMM_SMEM ((2*GS_A + 2*GS_B) * 4)   // 110592 B

template <int STORE_TF32>
__device__ __forceinline__ void gemm_body(
    const unsigned* __restrict__ A, const unsigned* __restrict__ W,
    const float* __restrict__ bias, void* __restrict__ Cout,
    float oscale, int m0, int n0, unsigned* sm)
{
    unsigned* As = sm;
    unsigned* Bs = sm + 2 * GS_A;

    int tid = threadIdx.x;
    int w = tid >> 5, lane = tid & 31;
    int wm = (w & 1) * 64, wn = (w >> 1) * 64;
    int r = lane >> 2, cc = lane & 3;

    const unsigned* Abase = A + (size_t)m0 * EE;
    const unsigned* Wbase = W + (size_t)n0 * EE;

    float acc[4][8][4];
    #pragma unroll
    for (int mi = 0; mi < 4; mi++)
        #pragma unroll
        for (int ni = 0; ni < 8; ni++)
            #pragma unroll
            for (int j = 0; j < 4; j++) acc[mi][ni][j] = 0.f;

    auto fill = [&](int s, int k0) {
        #pragma unroll
        for (int i = 0; i < 4; i++) {
            int lin = tid + i * 256;
            int rr = lin >> 3, kc = (lin & 7) << 2;
            cp16(&As[s * GS_A + rr * 36 + kc], Abase + (size_t)rr * EE + k0 + kc);
        }
        #pragma unroll
        for (int i = 0; i < 8; i++) {
            int lin = tid + i * 256;
            int rr = lin >> 3, kc = (lin & 7) << 2;
            cp16(&Bs[s * GS_B + rr * 36 + kc], Wbase + (size_t)rr * EE + k0 + kc);
        }
        asm volatile("cp.async.commit_group;");
    };

    fill(0, 0);
    for (int it = 0; it < EE / 32; it++) {
        int cur = it & 1;
        if (it + 1 < EE / 32) {
            fill(1 - cur, (it + 1) * 32);
            asm volatile("cp.async.wait_group 1;");
        } else {
            asm volatile("cp.async.wait_group 0;");
        }
        __syncthreads();

        const unsigned* Ac = &As[cur * GS_A];
        const unsigned* Bc = &Bs[cur * GS_B];
        #pragma unroll
        for (int kk = 0; kk < 32; kk += 8) {
            unsigned af[4][4], bf[8][2];
            #pragma unroll
            for (int mi = 0; mi < 4; mi++) {
                int mb = wm + mi * 16;
                af[mi][0] = Ac[(mb + r) * 36 + kk + cc];
                af[mi][1] = Ac[(mb + 8 + r) * 36 + kk + cc];
                af[mi][2] = Ac[(mb + r) * 36 + kk + cc + 4];
                af[mi][3] = Ac[(mb + 8 + r) * 36 + kk + cc + 4];
            }
            #pragma unroll
            for (int ni = 0; ni < 8; ni++) {
                int nb = wn + ni * 8 + r;
                bf[ni][0] = Bc[nb * 36 + kk + cc];
                bf[ni][1] = Bc[nb * 36 + kk + cc + 4];
            }
            #pragma unroll
            for (int mi = 0; mi < 4; mi++)
                #pragma unroll
                for (int ni = 0; ni < 8; ni++)
                    mma_tf32(acc[mi][ni], af[mi][0], af[mi][1], af[mi][2], af[mi][3],
                             bf[ni][0], bf[ni][1]);
        }
        __syncthreads();
    }

    #pragma unroll
    for (int mi = 0; mi < 4; mi++) {
        int m = m0 + wm + mi * 16 + r;
        #pragma unroll
        for (int ni = 0; ni < 8; ni++) {
            int n = n0 + wn + ni * 8 + cc * 2;
            float2 bv = *reinterpret_cast<const float2*>(&bias[n]);
            float o0 = (acc[mi][ni][0] + bv.x) * oscale;
            float o1 = (acc[mi][ni][1] + bv.y) * oscale;
            float o2 = (acc[mi][ni][2] + bv.x) * oscale;
            float o3 = (acc[mi][ni][3] + bv.y) * oscale;
            if (STORE_TF32) {
                unsigned* C = (unsigned*)Cout;
                *reinterpret_cast<uint2*>(&C[(size_t)m * EE + n]) =
                    make_uint2(f2tf32(o0), f2tf32(o1));
                *reinterpret_cast<uint2*>(&C[(size_t)(m + 8) * EE + n]) =
                    make_uint2(f2tf32(o2), f2tf32(o3));
            } else {
                float* C = (float*)Cout;
                *reinterpret_cast<float2*>(&C[(size_t)m * EE + n]) = make_float2(o0, o1);
                *reinterpret_cast<float2*>(&C[(size_t)(m + 8) * EE + n]) = make_float2(o2, o3);
            }
        }
    }
}

// Fused Q/K/V projection: grid.z selects weight/bias/output/oscale.
__global__ __launch_bounds__(256) void qkv_gemm_tc(
    const unsigned* __restrict__ A, const unsigned* __restrict__ Wall,
    const float* __restrict__ bq, const float* __restrict__ bk,
    const float* __restrict__ bv,
    unsigned* __restrict__ Qo, unsigned* __restrict__ Ko, unsigned* __restrict__ Vo)
{
    extern __shared__ unsigned sm[];
    int z = blockIdx.z;
    const unsigned* W = Wall + (size_t)z * EE * EE;
    const float* bias = (z == 0) ? bq : (z == 1) ? bk : bv;
    unsigned* C = (z == 0) ? Qo : (z == 1) ? Ko : Vo;
    float oscale = (z == 0) ? 0.125f : 1.0f;
    gemm_body<1>(A, W, bias, C, oscale, blockIdx.y * 128, blockIdx.x * 256, sm);
}

// O-projection (fp32 output).
__global__ __launch_bounds__(256) void ogemm_tc(
    const unsigned* __restrict__ A, const unsigned* __restrict__ W,
    const float* __restrict__ bias, float* __restrict__ Cout)
{
    extern __shared__ unsigned sm[];
    gemm_body<0>(A, W, bias, Cout, 1.0f, blockIdx.y * 128, blockIdx.x * 256, sm);
}

// ---------------------------------------------------------------------------
// Tensor-core flash attention over compacted keys, double-buffered cp.async
// gather. K/V rows fetched by pseudo-position index for tile t+1 while
// computing tile t. Pads (slot >= cnt) gather row 0, masked via register
// compare. 1 block barrier + 1 syncwarp per tile.
// ---------------------------------------------------------------------------
// smem words: Ks 2*64*68=8704, Vs 8704, Ps 4*32*68=8704, krs 2*64=128
#define ATTN_SMEM ((8704*3 + 128) * 4)   // 104960 B

__global__ __launch_bounds__(128) void attn_tc(
    const unsigned* __restrict__ Q, const unsigned* __restrict__ K,
    const unsigned* __restrict__ V, const int* __restrict__ idxp,
    const int* __restrict__ cntp, unsigned* __restrict__ O)
{
    extern __shared__ unsigned smn[];
    unsigned (*Ks)[64][68] = (unsigned (*)[64][68])smn;          // [2][64][68]
    unsigned (*Vs)[64][68] = (unsigned (*)[64][68])(smn + 8704); // [2][64][68]
    unsigned (*Ps)[68] = (unsigned (*)[68])(smn + 17408);        // [4*32][68]
    int* krs = (int*)(smn + 26112);                              // [2][64]

    int b = blockIdx.z, h = blockIdx.y;
    int q0 = blockIdx.x * 128;
    int t = threadIdx.x, w = t >> 5, lane = t & 31;
    int r = lane >> 2, cc = lane & 3;
    size_t hbase = ((size_t)(b * HH + h)) * LL * HD;
    unsigned (*Pw)[68] = &Ps[w * 32];

    int cnt = cntp[b];
    int ntiles = (cnt + 63) >> 6;

    // Gather fill for K/V tile into stage s using keyrows krs[s].
    auto fillKV = [&](int s) {
        #pragma unroll
        for (int i = 0; i < 8; i++) {
            int lin = t + i * 128;
            int row = lin >> 4, chunk = lin & 15, c = chunk << 2;
            int g = krs[s * 64 + row];
            size_t rb = hbase + (size_t)g * HD + c;
            cp16(&Ks[s][row][c], K + rb);
            cp16(&Vs[s][row][c], V + rb);
        }
        asm volatile("cp.async.commit_group;");
    };

    // Stage this warp's 32 Q rows, extract A-fragments.
    {
        const uint4* Qg = (const uint4*)(Q + hbase + (size_t)(q0 + w * 32) * HD);
        #pragma unroll
        for (int i = 0; i < 16; i++) {
            int lin = lane + i * 32;
            int row = lin >> 4, c = (lin & 15) << 2;
            *reinterpret_cast<uint4*>(&Pw[row][c]) = Qg[lin];
        }
    }
    __syncwarp();
    unsigned qa[2][8][4];
    #pragma unroll
    for (int mi = 0; mi < 2; mi++)
        #pragma unroll
        for (int ks = 0; ks < 8; ks++) {
            qa[mi][ks][0] = Pw[mi * 16 + r][ks * 8 + cc];
            qa[mi][ks][1] = Pw[mi * 16 + 8 + r][ks * 8 + cc];
            qa[mi][ks][2] = Pw[mi * 16 + r][ks * 8 + cc + 4];
            qa[mi][ks][3] = Pw[mi * 16 + 8 + r][ks * 8 + cc + 4];
        }

    // Prime stage 0.
    if (t < 64) krs[t] = (t < cnt) ? idxp[b * LL + t] : 0;
    __syncthreads();
    fillKV(0);

    float of[2][8][4];
    #pragma unroll
    for (int mi = 0; mi < 2; mi++)
        #pragma unroll
        for (int nf = 0; nf < 8; nf++)
            #pragma unroll
            for (int j = 0; j < 4; j++) of[mi][nf][j] = 0.f;
    float mA[2] = {-1e30f, -1e30f}, mB[2] = {-1e30f, -1e30f};
    float lA[2] = {0.f, 0.f},       lB[2] = {0.f, 0.f};

    for (int tt = 0; tt < ntiles; tt++) {
        int cur = tt & 1;
        int k0 = tt * 64;
        asm volatile("cp.async.wait_group 0;");
        // Stage next tile's keyrows (other buffer).
        if (tt + 1 < ntiles && t < 64) {
            int slot = (tt + 1) * 64 + t;
            krs[(1 - cur) * 64 + t] = (slot < cnt) ? idxp[b * LL + slot] : 0;
        }
        __syncthreads();
        if (tt + 1 < ntiles) fillKV(1 - cur);

        // S = Q K^T : 32 rows x 64 keys per warp (K-frags shared across mi).
        float sc[2][8][4];
        #pragma unroll
        for (int mi = 0; mi < 2; mi++)
            #pragma unroll
            for (int nf = 0; nf < 8; nf++)
                #pragma unroll
                for (int j = 0; j < 4; j++) sc[mi][nf][j] = 0.f;
        #pragma unroll
        for (int ks = 0; ks < 8; ks++)
            #pragma unroll
            for (int nf = 0; nf < 8; nf++) {
                unsigned b0 = Ks[cur][nf * 8 + r][ks * 8 + cc];
                unsigned b1 = Ks[cur][nf * 8 + r][ks * 8 + cc + 4];
                #pragma unroll
                for (int mi = 0; mi < 2; mi++)
                    mma_tf32(sc[mi][nf], qa[mi][ks][0], qa[mi][ks][1],
                             qa[mi][ks][2], qa[mi][ks][3], b0, b1);
            }

        // pad-mask via cnt compare + online softmax
        #pragma unroll
        for (int mi = 0; mi < 2; mi++) {
            float rA = -1e30f, rB = -1e30f;
            #pragma unroll
            for (int nf = 0; nf < 8; nf++) {
                int key0 = k0 + nf * 8 + 2 * cc;
                bool u0 = key0 < cnt, u1 = key0 + 1 < cnt;
                sc[mi][nf][0] = u0 ? sc[mi][nf][0] : -1e10f;
                sc[mi][nf][1] = u1 ? sc[mi][nf][1] : -1e10f;
                sc[mi][nf][2] = u0 ? sc[mi][nf][2] : -1e10f;
                sc[mi][nf][3] = u1 ? sc[mi][nf][3] : -1e10f;
                rA = fmaxf(rA, fmaxf(sc[mi][nf][0], sc[mi][nf][1]));
                rB = fmaxf(rB, fmaxf(sc[mi][nf][2], sc[mi][nf][3]));
            }
            rA = fmaxf(rA, __shfl_xor_sync(0xffffffffu, rA, 1));
            rA = fmaxf(rA, __shfl_xor_sync(0xffffffffu, rA, 2));
            rB = fmaxf(rB, __shfl_xor_sync(0xffffffffu, rB, 1));
            rB = fmaxf(rB, __shfl_xor_sync(0xffffffffu, rB, 2));

            float mAn = fmaxf(mA[mi], rA), mBn = fmaxf(mB[mi], rB);
            float cA = __expf(mA[mi] - mAn), cB = __expf(mB[mi] - mBn);
            mA[mi] = mAn; mB[mi] = mBn;
            lA[mi] *= cA; lB[mi] *= cB;

            float sumA = 0.f, sumB = 0.f;
            #pragma unroll
            for (int nf = 0; nf < 8; nf++) {
                float p0 = __expf(sc[mi][nf][0] - mAn), p1 = __expf(sc[mi][nf][1] - mAn);
                float p2 = __expf(sc[mi][nf][2] - mBn), p3 = __expf(sc[mi][nf][3] - mBn);
                sumA += p0 + p1; sumB += p2 + p3;
                of[mi][nf][0] *= cA; of[mi][nf][1] *= cA;
                of[mi][nf][2] *= cB; of[mi][nf][3] *= cB;
                *reinterpret_cast<uint2*>(&Pw[mi * 16 + r][nf * 8 + 2 * cc]) =
                    make_uint2(f2tf32(p0), f2tf32(p1));
                *reinterpret_cast<uint2*>(&Pw[mi * 16 + 8 + r][nf * 8 + 2 * cc]) =
                    make_uint2(f2tf32(p2), f2tf32(p3));
            }
            sumA += __shfl_xor_sync(0xffffffffu, sumA, 1);
            sumA += __shfl_xor_sync(0xffffffffu, sumA, 2);
            sumB += __shfl_xor_sync(0xffffffffu, sumB, 1);
            sumB += __shfl_xor_sync(0xffffffffu, sumB, 2);
            lA[mi] += sumA; lB[mi] += sumB;
        }
        __syncwarp();   // P buffer is warp-local

        // O += P V  (V-frags shared across mi)
        #pragma unroll
        for (int ks = 0; ks < 8; ks++) {
            unsigned pa[2][4];
            #pragma unroll
            for (int mi = 0; mi < 2; mi++) {
                pa[mi][0] = Pw[mi * 16 + r][ks * 8 + cc];
                pa[mi][1] = Pw[mi * 16 + 8 + r][ks * 8 + cc];
                pa[mi][2] = Pw[mi * 16 + r][ks * 8 + cc + 4];
                pa[mi][3] = Pw[mi * 16 + 8 + r][ks * 8 + cc + 4];
            }
            #pragma unroll
            for (int nf = 0; nf < 8; nf++) {
                unsigned b0 = Vs[cur][ks * 8 + cc][nf * 8 + r];
                unsigned b1 = Vs[cur][ks * 8 + cc + 4][nf * 8 + r];
                #pragma unroll
                for (int mi = 0; mi < 2; mi++)
                    mma_tf32(of[mi][nf], pa[mi][0], pa[mi][1], pa[mi][2], pa[mi][3],
                             b0, b1);
            }
        }
    }

    // Normalize + store (standard layout, tf32 for the O-projection GEMM).
    #pragma unroll
    for (int mi = 0; mi < 2; mi++) {
        float iA = 1.f / lA[mi], iB = 1.f / lB[mi];
        size_t rowA = (size_t)b * LL + q0 + w * 32 + mi * 16 + r;
        #pragma unroll
        for (int nf = 0; nf < 8; nf++) {
            int col = h * HD + nf * 8 + 2 * cc;
            *reinterpret_cast<uint2*>(&O[rowA * EE + col]) =
                make_uint2(f2tf32(of[mi][nf][0] * iA), f2tf32(of[mi][nf][1] * iA));
            *reinterpret_cast<uint2*>(&O[(rowA + 8) * EE + col]) =
                make_uint2(f2tf32(of[mi][nf][2] * iB), f2tf32(of[mi][nf][3] * iB));
        }
    }
}

// ---------------------------------------------------------------------------
// Launch
// ---------------------------------------------------------------------------
extern "C" void kernel_launch(void* const* d_in, const int* in_sizes, int n_in,
                              void* d_out, int out_size) {
    const float* x    = (const float*)d_in[0];
    const int*   mask = (const int*)  d_in[1];
    const float* Wq   = (const float*)d_in[2];
    const float* bq   = (const float*)d_in[3];
    const float* Wk   = (const float*)d_in[4];
    const float* bk   = (const float*)d_in[5];
    const float* Wv   = (const float*)d_in[6];
    const float* bv   = (const float*)d_in[7];
    const float* Wo   = (const float*)d_in[8];
    const float* bo   = (const float*)d_in[9];
    float* out = (float*)d_out;

    unsigned *Qp, *Kp, *Vp, *Ap, *Xp, *Wp;
    int *idxp, *cntp;
    cudaGetSymbolAddress((void**)&Qp, g_Q);
    cudaGetSymbolAddress((void**)&Kp, g_K);
    cudaGetSymbolAddress((void**)&Vp, g_V);
    cudaGetSymbolAddress((void**)&Ap, g_A);
    cudaGetSymbolAddress((void**)&Xp, g_X);
    cudaGetSymbolAddress((void**)&Wp, g_Wc);
    cudaGetSymbolAddress((void**)&idxp, g_idx);
    cudaGetSymbolAddress((void**)&cntp, g_cnt);

    static int attr_set = 0;
    if (!attr_set) {
        cudaFuncSetAttribute(qkv_gemm_tc, cudaFuncAttributeMaxDynamicSharedMemorySize,
                             GEMM_SMEM);
        cudaFuncSetAttribute(ogemm_tc, cudaFuncAttributeMaxDynamicSharedMemorySize,
                             GEMM_SMEM);
        cudaFuncSetAttribute(attn_tc, cudaFuncAttributeMaxDynamicSharedMemorySize,
                             ATTN_SMEM);
        attr_set = 1;
    }

    const int n4x = MM * EE / 4;
    const int n4w = EE * EE / 4;
    conv_tf32_kernel<<<(n4x + 255) / 256, 256>>>((const float4*)x, (uint4*)Xp, n4x);
    dim3 wgrid((n4w + 255) / 256, 4);
    conv_w4_kernel<<<wgrid, 256>>>((const float4*)Wq, (const float4*)Wk,
                                   (const float4*)Wv, (const float4*)Wo,
                                   (uint4*)Wp, n4w);
    compact_mask_kernel<<<BB, 1024>>>(mask, idxp, cntp);

    dim3 qkv_grid(EE / 256, MM / 128, 3);   // (4, 64, 3)
    qkv_gemm_tc<<<qkv_grid, 256, GEMM_SMEM>>>(Xp, Wp, bq, bk, bv, Qp, Kp, Vp);

    dim3 attn_grid(LL / 128, HH, BB);       // (16, 16, 4)
    attn_tc<<<attn_grid, 128, ATTN_SMEM>>>(Qp, Kp, Vp, idxp, cntp, Ap);

    dim3 ogrid(EE / 256, MM / 128);         // (4, 64)
    ogemm_tc<<<ogrid, 256, GEMM_SMEM>>>(Ap, Wp + 3 * EE * EE, bo, out);
}